// round 1
// baseline (speedup 1.0000x reference)
#include <cuda_runtime.h>

// ---------------------------------------------------------------------------
// GraphAttention: B=128, N=256, F=512, H=8, F_=64
// Inputs (metadata order):
//   d_in[0] X          [128,256,512] f32
//   d_in[1] A          [128,256,256] f32 (binary)
//   d_in[2] kernels    [8,512,64]    f32
//   d_in[3] biases     [8,64]        f32
//   d_in[4] attn_self  [8,64]        f32
//   d_in[5] attn_neigh [8,64]        f32
//   d_in[6] alpha      [128,128]     f32
// Output d_out: concat( output [128,256,512], dense4 [128,256,256] ) f32
// ---------------------------------------------------------------------------

// Scratch (allocation-free rule: __device__ globals)
__device__ float g_W[512 * 512];          // W[f][h*64+k]
__device__ float g_feats[16777216];       // [b*256+n][512] = [32768][512]
__device__ float g_asn[524288];           // a_self [8][32768] then a_neigh [8][32768]
__device__ float g_rowsum[128];           // rowsum of alpha
__device__ float g_s[128];                // per-batch pooled-attn scalar

// ---------------------------------------------------------------------------
// K0: transpose kernels -> W, alpha row sums, zero g_s
// ---------------------------------------------------------------------------
__global__ void prep_kernel(const float* __restrict__ kernels,
                            const float* __restrict__ alpha) {
    int idx = blockIdx.x * 256 + threadIdx.x;
    if (idx < 512 * 512) {
        int f = idx >> 9, hk = idx & 511;
        int h = hk >> 6, k = hk & 63;
        g_W[idx] = kernels[(h * 512 + f) * 64 + k];
    }
    if (idx < 128) {
        float s = 0.f;
        const float* ar = alpha + idx * 128;
#pragma unroll 4
        for (int k = 0; k < 128; ++k) s += ar[k];
        g_rowsum[idx] = s;
        g_s[idx] = 0.f;
    }
}

// ---------------------------------------------------------------------------
// K1: feats = X @ W   ([32768,512] x [512,512] -> g_feats)
// 128x128 tile, BK=16, 256 threads, 8x8 per thread.
// ---------------------------------------------------------------------------
__global__ __launch_bounds__(256, 2) void gemm_kernel(const float* __restrict__ X) {
    __shared__ float As[16][128];
    __shared__ float Bs[16][128];
    const int tid = threadIdx.x;
    const int bm = blockIdx.y * 128;
    const int bn = blockIdx.x * 128;
    const int tr = tid >> 4, tc = tid & 15;
    const int tm = tr * 8, tn = tc * 8;

    float acc[8][8];
#pragma unroll
    for (int i = 0; i < 8; ++i)
#pragma unroll
        for (int j = 0; j < 8; ++j) acc[i][j] = 0.f;

    const int ar = tid >> 1;       // 0..127
    const int ac = (tid & 1) * 8;  // 0 or 8
    const int br = tid >> 4;       // 0..15
    const int bc = (tid & 15) * 8; // 0..120

    for (int k0 = 0; k0 < 512; k0 += 16) {
        float4 a0 = *(const float4*)(X + (size_t)(bm + ar) * 512 + k0 + ac);
        float4 a1 = *(const float4*)(X + (size_t)(bm + ar) * 512 + k0 + ac + 4);
        As[ac + 0][ar] = a0.x; As[ac + 1][ar] = a0.y;
        As[ac + 2][ar] = a0.z; As[ac + 3][ar] = a0.w;
        As[ac + 4][ar] = a1.x; As[ac + 5][ar] = a1.y;
        As[ac + 6][ar] = a1.z; As[ac + 7][ar] = a1.w;
        *(float4*)(&Bs[br][bc])     = *(const float4*)(g_W + (size_t)(k0 + br) * 512 + bn + bc);
        *(float4*)(&Bs[br][bc + 4]) = *(const float4*)(g_W + (size_t)(k0 + br) * 512 + bn + bc + 4);
        __syncthreads();
#pragma unroll
        for (int kk = 0; kk < 16; ++kk) {
            float a[8], b[8];
#pragma unroll
            for (int i = 0; i < 8; ++i) a[i] = As[kk][tm + i];
#pragma unroll
            for (int j = 0; j < 8; ++j) b[j] = Bs[kk][tn + j];
#pragma unroll
            for (int i = 0; i < 8; ++i)
#pragma unroll
                for (int j = 0; j < 8; ++j) acc[i][j] += a[i] * b[j];
        }
        __syncthreads();
    }
#pragma unroll
    for (int i = 0; i < 8; ++i) {
        float* orow = g_feats + (size_t)(bm + tm + i) * 512 + bn + tn;
        *(float4*)(orow)     = make_float4(acc[i][0], acc[i][1], acc[i][2], acc[i][3]);
        *(float4*)(orow + 4) = make_float4(acc[i][4], acc[i][5], acc[i][6], acc[i][7]);
    }
}

// ---------------------------------------------------------------------------
// K2: a_self[h][row] = feats[row][h*64:].attn_self[h]; same for a_neigh.
// One warp per row, 8 rows per block.
// ---------------------------------------------------------------------------
__global__ void asn_kernel(const float* __restrict__ attn_self,
                           const float* __restrict__ attn_neigh) {
    __shared__ float sr[4096];
    __shared__ float ss[512], sn[512];
    int t = threadIdx.x;
    for (int u = t; u < 512; u += 256) { ss[u] = attn_self[u]; sn[u] = attn_neigh[u]; }
    size_t base = (size_t)blockIdx.x * 4096;
    for (int u = t; u < 4096; u += 256) sr[u] = g_feats[base + u];
    __syncthreads();

    int warp = t >> 5, lane = t & 31;
    int h = lane >> 2, kb = (lane & 3) << 4;
    const float* fr = sr + warp * 512;
    int off = h * 64 + kb;
    float ps = 0.f, pn = 0.f;
#pragma unroll
    for (int u = 0; u < 16; ++u) {
        float fv = fr[off + u];
        ps += fv * ss[off + u];
        pn += fv * sn[off + u];
    }
    ps += __shfl_xor_sync(0xffffffffu, ps, 1);
    ps += __shfl_xor_sync(0xffffffffu, ps, 2);
    pn += __shfl_xor_sync(0xffffffffu, pn, 1);
    pn += __shfl_xor_sync(0xffffffffu, pn, 2);
    if ((lane & 3) == 0) {
        int row = blockIdx.x * 8 + warp;
        g_asn[h * 32768 + row] = ps;
        g_asn[262144 + h * 32768 + row] = pn;
    }
}

// ---------------------------------------------------------------------------
// K3: fused attention. Block = (itile 16 rows, batch b). Loop over 8 heads:
//  logits -> softmax -> view accumulation -> node = attn @ feats (+bias, relu)
// Then view store + pooled partial for s[b].
// Dynamic smem: 116352 B.
// ---------------------------------------------------------------------------
__global__ __launch_bounds__(256, 1) void attn_kernel(
    const float* __restrict__ Aadj, const float* __restrict__ biases,
    float* __restrict__ out, float* __restrict__ view) {
    extern __shared__ float sm[];
    float* sA     = sm;          // 4096: A tile [16][256]
    float* sview  = sm + 4096;   // 4096: head-avg attn accumulation
    float* sw     = sm + 8192;   // 4096: current head attn weights
    float* sfeat  = sm + 12288;  // 16384: feats tile [256][64] (reused as reduce buf)
    float* sneigh = sm + 28672;  // 256
    float* ssel   = sneigh + 256; // 16
    float* sred   = ssel + 16;    // 128 (16 rows x 8 warps)
    float* sinv   = sred + 128;   // 16

    const int b = blockIdx.y;
    const int i0 = blockIdx.x * 16;
    const int t = threadIdx.x;
    const int lane = t & 31, warp = t >> 5;
    const int kq = t & 15, jg = t >> 4;

    for (int u = t; u < 4096; u += 256) {
        sA[u] = Aadj[((size_t)b * 256 + i0 + (u >> 8)) * 256 + (u & 255)];
        sview[u] = 0.f;
    }

    float4* sf4 = (float4*)sfeat;

    for (int h = 0; h < 8; ++h) {
        const float* fb = g_feats + ((size_t)b * 256) * 512 + h * 64;
        for (int u = t; u < 4096; u += 256) {
            int j = u >> 4, c = u & 15;
            sf4[u] = *(const float4*)(fb + (size_t)j * 512 + c * 4);
        }
        sneigh[t] = g_asn[262144 + h * 32768 + b * 256 + t];
        if (t < 16) ssel[t] = g_asn[h * 32768 + b * 256 + i0 + t];
        __syncthreads();

        // --- logits + exp: thread t owns column j=t for all 16 rows ---
        float w[16];
        float an = sneigh[t];
#pragma unroll
        for (int i = 0; i < 16; ++i) {
            float z = ssel[i] + an;
            z = (z > 0.f) ? z : 0.2f * z;
            z += -1.0e10f * (1.f - sA[i * 256 + t]);
            w[i] = __expf(z);  // masked -> exp(-1e10) = 0
        }
        // --- row sums (softmax denominators) ---
#pragma unroll
        for (int i = 0; i < 16; ++i) {
            float v = w[i];
#pragma unroll
            for (int o = 16; o > 0; o >>= 1) v += __shfl_xor_sync(0xffffffffu, v, o);
            if (lane == 0) sred[i * 8 + warp] = v;
        }
        __syncthreads();
        if (t < 16) {
            float s = 0.f;
#pragma unroll
            for (int g = 0; g < 8; ++g) s += sred[t * 8 + g];
            sinv[t] = 1.f / s;
        }
        __syncthreads();
#pragma unroll
        for (int i = 0; i < 16; ++i) {
            float a = w[i] * sinv[i];
            sview[i * 256 + t] += 0.125f * a;  // mean over 8 heads
            sw[i * 256 + t] = a;
        }
        __syncthreads();

        // --- node aggregation: out[i][k] = sum_j attn[i][j]*feats[j][k] ---
        // thread (kq: 4 k's, jg: 16 j's); 16 rows in registers
        float4 acc[16];
#pragma unroll
        for (int i = 0; i < 16; ++i) acc[i] = make_float4(0.f, 0.f, 0.f, 0.f);
#pragma unroll 4
        for (int s = 0; s < 16; ++s) {
            int j = jg * 16 + s;
            float4 f = sf4[j * 16 + kq];
#pragma unroll
            for (int i = 0; i < 16; ++i) {
                float wv = sw[i * 256 + j];
                acc[i].x += wv * f.x; acc[i].y += wv * f.y;
                acc[i].z += wv * f.z; acc[i].w += wv * f.w;
            }
        }
        __syncthreads();  // done reading sfeat; reuse it as reduce buffer
#pragma unroll
        for (int i = 0; i < 16; ++i) sf4[(jg * 16 + i) * 16 + kq] = acc[i];
        __syncthreads();
        // reduce 16 jg-partials, add bias, relu, store
#pragma unroll
        for (int r = 0; r < 4; ++r) {
            int o = t + 256 * r;
            int i = o >> 6, k = o & 63;
            float s = 0.f;
#pragma unroll
            for (int g = 0; g < 16; ++g) s += sfeat[(g * 16 + i) * 64 + k];
            s += biases[h * 64 + k];
            out[((size_t)b * 256 + i0 + i) * 512 + h * 64 + k] = fmaxf(s, 0.f);
        }
        __syncthreads();
    }

    // --- view store ---
    for (int u = t; u < 4096; u += 256)
        view[((size_t)b * 256 + i0 + (u >> 8)) * 256 + (u & 255)] = sview[u];

    // --- pooled (2x2 max) partial contribution to s[b] ---
    // s[b] = sum_{pi,pj} pooled[pi][pj] * rowsum_alpha[pj]
    float part = 0.f;
    for (int u = t; u < 1024; u += 256) {
        int pi = u >> 7, pj = u & 127;
        const float* v0 = sview + (2 * pi) * 256 + 2 * pj;
        const float* v1 = v0 + 256;
        float m = fmaxf(fmaxf(v0[0], v0[1]), fmaxf(v1[0], v1[1]));
        part += m * g_rowsum[pj];
    }
#pragma unroll
    for (int o = 16; o > 0; o >>= 1) part += __shfl_xor_sync(0xffffffffu, part, o);
    if (lane == 0) atomicAdd(&g_s[b], part);
}

// ---------------------------------------------------------------------------
// K4: dense4 = (view + I < sigmoid(s[b])) ? 1 : 0   (in-place in d_out)
// ---------------------------------------------------------------------------
__global__ void binarize_kernel(float* __restrict__ view) {
    size_t idx = (size_t)blockIdx.x * 256 + threadIdx.x;  // 8388608 total
    int b = (int)(idx >> 16);
    int ij = (int)(idx & 65535);
    int i = ij >> 8, j = ij & 255;
    float th = 1.f / (1.f + expf(-g_s[b]));
    float v = view[idx] + ((i == j) ? 1.f : 0.f);
    view[idx] = (v < th) ? 1.f : 0.f;
}

// ---------------------------------------------------------------------------
extern "C" void kernel_launch(void* const* d_in, const int* in_sizes, int n_in,
                              void* d_out, int out_size) {
    const float* X          = (const float*)d_in[0];
    const float* Aadj       = (const float*)d_in[1];
    const float* kernels    = (const float*)d_in[2];
    const float* biases     = (const float*)d_in[3];
    const float* attn_self  = (const float*)d_in[4];
    const float* attn_neigh = (const float*)d_in[5];
    const float* alpha      = (const float*)d_in[6];
    float* out  = (float*)d_out;            // [128,256,512]
    float* view = out + 16777216;           // [128,256,256] (dense4 region)

    const int ATTN_SMEM = 29088 * 4;  // 116352 B
    cudaFuncSetAttribute(attn_kernel, cudaFuncAttributeMaxDynamicSharedMemorySize, ATTN_SMEM);

    prep_kernel<<<1024, 256>>>(kernels, alpha);
    gemm_kernel<<<dim3(4, 256), 256>>>(X);
    asn_kernel<<<4096, 256>>>(attn_self, attn_neigh);
    attn_kernel<<<dim3(16, 128), 256, ATTN_SMEM>>>(Aadj, biases, out, view);
    binarize_kernel<<<32768, 256>>>(view);
}

// round 4
// speedup vs baseline: 1.3849x; 1.3849x over previous
#include <cuda_runtime.h>

// ---------------------------------------------------------------------------
// GraphAttention: B=128, N=256, F=512, H=8, F_=64
// Output d_out: concat( output [128,256,512], dense4 [128,256,256] ) f32
// ---------------------------------------------------------------------------

__device__ float g_W[512 * 512];          // W[f][h*64+k]
__device__ float g_feats[16777216];       // [32768][512]
__device__ float g_asn[524288];           // a_self [8][32768] then a_neigh [8][32768]
__device__ float g_rowsum[128];           // rowsum of alpha
__device__ float g_s[128];                // per-batch pooled-attn scalar

// ---------------------------------------------------------------------------
// K0: transpose kernels -> W, alpha row sums, zero g_s
// ---------------------------------------------------------------------------
__global__ void prep_kernel(const float* __restrict__ kernels,
                            const float* __restrict__ alpha) {
    int idx = blockIdx.x * 256 + threadIdx.x;
    if (idx < 512 * 512) {
        int f = idx >> 9, hk = idx & 511;
        int h = hk >> 6, k = hk & 63;
        g_W[idx] = kernels[(h * 512 + f) * 64 + k];
    }
    if (idx < 128) {
        float s = 0.f;
        const float* ar = alpha + idx * 128;
#pragma unroll 4
        for (int k = 0; k < 128; ++k) s += ar[k];
        g_rowsum[idx] = s;
        g_s[idx] = 0.f;
    }
}

// ---------------------------------------------------------------------------
// K1: feats = X @ W   ([32768,512] x [512,512])
// ---------------------------------------------------------------------------
__global__ __launch_bounds__(256, 2) void gemm_kernel(const float* __restrict__ X) {
    __shared__ float As[16][128];
    __shared__ float Bs[16][128];
    const int tid = threadIdx.x;
    const int bm = blockIdx.y * 128;
    const int bn = blockIdx.x * 128;
    const int tr = tid >> 4, tc = tid & 15;
    const int tm = tr * 8, tn = tc * 8;

    float acc[8][8];
#pragma unroll
    for (int i = 0; i < 8; ++i)
#pragma unroll
        for (int j = 0; j < 8; ++j) acc[i][j] = 0.f;

    const int ar = tid >> 1;
    const int ac = (tid & 1) * 8;
    const int br = tid >> 4;
    const int bc = (tid & 15) * 8;

    for (int k0 = 0; k0 < 512; k0 += 16) {
        float4 a0 = *(const float4*)(X + (size_t)(bm + ar) * 512 + k0 + ac);
        float4 a1 = *(const float4*)(X + (size_t)(bm + ar) * 512 + k0 + ac + 4);
        As[ac + 0][ar] = a0.x; As[ac + 1][ar] = a0.y;
        As[ac + 2][ar] = a0.z; As[ac + 3][ar] = a0.w;
        As[ac + 4][ar] = a1.x; As[ac + 5][ar] = a1.y;
        As[ac + 6][ar] = a1.z; As[ac + 7][ar] = a1.w;
        *(float4*)(&Bs[br][bc])     = *(const float4*)(g_W + (size_t)(k0 + br) * 512 + bn + bc);
        *(float4*)(&Bs[br][bc + 4]) = *(const float4*)(g_W + (size_t)(k0 + br) * 512 + bn + bc + 4);
        __syncthreads();
#pragma unroll
        for (int kk = 0; kk < 16; ++kk) {
            float a[8], b[8];
#pragma unroll
            for (int i = 0; i < 8; ++i) a[i] = As[kk][tm + i];
#pragma unroll
            for (int j = 0; j < 8; ++j) b[j] = Bs[kk][tn + j];
#pragma unroll
            for (int i = 0; i < 8; ++i)
#pragma unroll
                for (int j = 0; j < 8; ++j) acc[i][j] += a[i] * b[j];
        }
        __syncthreads();
    }
#pragma unroll
    for (int i = 0; i < 8; ++i) {
        float* orow = g_feats + (size_t)(bm + tm + i) * 512 + bn + tn;
        *(float4*)(orow)     = make_float4(acc[i][0], acc[i][1], acc[i][2], acc[i][3]);
        *(float4*)(orow + 4) = make_float4(acc[i][4], acc[i][5], acc[i][6], acc[i][7]);
    }
}

// ---------------------------------------------------------------------------
// K2: a_self / a_neigh dot products
// ---------------------------------------------------------------------------
__global__ void asn_kernel(const float* __restrict__ attn_self,
                           const float* __restrict__ attn_neigh) {
    __shared__ float sr[4096];
    __shared__ float ss[512], sn[512];
    int t = threadIdx.x;
    for (int u = t; u < 512; u += 256) { ss[u] = attn_self[u]; sn[u] = attn_neigh[u]; }
    size_t base = (size_t)blockIdx.x * 4096;
    for (int u = t; u < 4096; u += 256) sr[u] = g_feats[base + u];
    __syncthreads();

    int warp = t >> 5, lane = t & 31;
    int h = lane >> 2, kb = (lane & 3) << 4;
    const float* fr = sr + warp * 512;
    int off = h * 64 + kb;
    float ps = 0.f, pn = 0.f;
#pragma unroll
    for (int u = 0; u < 16; ++u) {
        float fv = fr[off + u];
        ps += fv * ss[off + u];
        pn += fv * sn[off + u];
    }
    ps += __shfl_xor_sync(0xffffffffu, ps, 1);
    ps += __shfl_xor_sync(0xffffffffu, ps, 2);
    pn += __shfl_xor_sync(0xffffffffu, pn, 1);
    pn += __shfl_xor_sync(0xffffffffu, pn, 2);
    if ((lane & 3) == 0) {
        int row = blockIdx.x * 8 + warp;
        g_asn[h * 32768 + row] = ps;
        g_asn[262144 + h * 32768 + row] = pn;
    }
}

// ---------------------------------------------------------------------------
// K3: fused attention v2. Block = (16-row tile, batch b), 256 thr, 2 CTA/SM.
// A-mask in a register bitmask; view accumulation in registers; 84.6KB smem.
// ---------------------------------------------------------------------------
__global__ __launch_bounds__(256, 2) void attn_kernel(
    const float* __restrict__ Aadj, const float* __restrict__ biases,
    float* __restrict__ out, float* __restrict__ view) {
    extern __shared__ float sm[];
    float* sfeat = sm;              // 16384 f: feats tile [256][64] / partial buf
    float* sw    = sm + 16384;      // 4096 f: attn weights [16][256]
    float* sbias = sm + 20480;      // 512 f
    float* ssel  = sm + 20992;      // 16 f
    float* sred  = sm + 21008;      // 128 f
    float* sinv  = sm + 21136;      // 16 f   (total 21152 f = 84608 B)
    float4* sf4 = (float4*)sfeat;

    const int b = blockIdx.y;
    const int i0 = blockIdx.x * 16;
    const int t = threadIdx.x;
    const int lane = t & 31, warp = t >> 5;
    const int kq = t & 15, jg = (t >> 4) & 7, ih = t >> 7;
    const int rbase = ih * 8;

    // A-mask bits for this thread's column t, rows i0..i0+15
    unsigned amask = 0u;
#pragma unroll
    for (int i = 0; i < 16; ++i)
        amask |= (Aadj[((size_t)b * 256 + i0 + i) * 256 + t] > 0.5f) ? (1u << i) : 0u;
    for (int u = t; u < 512; u += 256) sbias[u] = biases[u];

    float vacc[16];
#pragma unroll
    for (int i = 0; i < 16; ++i) vacc[i] = 0.f;

    for (int h = 0; h < 8; ++h) {
        const float* fb = g_feats + (size_t)b * 256 * 512 + h * 64;
        for (int u = t; u < 4096; u += 256) {
            int j = u >> 4, c = u & 15;
            sf4[u] = *(const float4*)(fb + (size_t)j * 512 + c * 4);
        }
        if (t < 16) ssel[t] = g_asn[h * 32768 + b * 256 + i0 + t];
        float an = g_asn[262144 + h * 32768 + b * 256 + t];
        __syncthreads();

        // --- logits + exp (thread t = column t, 16 rows) ---
        float w[16];
#pragma unroll
        for (int i = 0; i < 16; ++i) {
            float z = ssel[i] + an;
            z = (z > 0.f) ? z : 0.2f * z;
            w[i] = ((amask >> i) & 1u) ? __expf(z) : 0.f;
        }
        // --- softmax denominators ---
#pragma unroll
        for (int i = 0; i < 16; ++i) {
            float v = w[i];
#pragma unroll
            for (int o = 16; o > 0; o >>= 1) v += __shfl_xor_sync(0xffffffffu, v, o);
            if (lane == 0) sred[i * 8 + warp] = v;
        }
        __syncthreads();
        if (t < 16) {
            float s = 0.f;
#pragma unroll
            for (int g = 0; g < 8; ++g) s += sred[t * 8 + g];
            sinv[t] = 1.f / s;
        }
        __syncthreads();
#pragma unroll
        for (int i = 0; i < 16; ++i) {
            float a = w[i] * sinv[i];
            sw[i * 256 + t] = a;
            vacc[i] += 0.125f * a;   // head-mean view accumulation (registers)
        }
        __syncthreads();

        // --- node = attn @ feats: thread (kq, jg, ih): 8 rows x 4 k, 32 j ---
        float4 acc[8];
#pragma unroll
        for (int r = 0; r < 8; ++r) acc[r] = make_float4(0.f, 0.f, 0.f, 0.f);
#pragma unroll 4
        for (int s = 0; s < 32; ++s) {
            int j = jg * 32 + s;
            float4 f = sf4[j * 16 + kq];
#pragma unroll
            for (int r = 0; r < 8; ++r) {
                float wv = sw[(rbase + r) * 256 + j];
                acc[r].x += wv * f.x; acc[r].y += wv * f.y;
                acc[r].z += wv * f.z; acc[r].w += wv * f.w;
            }
        }
        __syncthreads();  // all sfeat reads done; reuse as partial buffer
#pragma unroll
        for (int r = 0; r < 8; ++r) sf4[(jg * 16 + rbase + r) * 16 + kq] = acc[r];
        __syncthreads();
        // reduce 8 j-partials, +bias, relu, store
#pragma unroll
        for (int rr = 0; rr < 4; ++rr) {
            int o = t + 256 * rr;
            int i = o >> 6, k = o & 63;
            float s = 0.f;
#pragma unroll
            for (int g = 0; g < 8; ++g) s += sfeat[(g * 16 + i) * 64 + k];
            s += sbias[h * 64 + k];
            out[((size_t)b * 256 + i0 + i) * 512 + h * 64 + k] = fmaxf(s, 0.f);
        }
        __syncthreads();
    }

    // --- view store (coalesced per row) ---
#pragma unroll
    for (int i = 0; i < 16; ++i)
        view[((size_t)b * 256 + i0 + i) * 256 + t] = vacc[i];

    // --- 2x2 max pool + s[b] partial, from registers ---
    float part = 0.f;
    float rs = g_rowsum[t >> 1];
#pragma unroll
    for (int pi = 0; pi < 8; ++pi) {
        float rm = fmaxf(vacc[2 * pi], vacc[2 * pi + 1]);
        rm = fmaxf(rm, __shfl_xor_sync(0xffffffffu, rm, 1));
        if (!(t & 1)) part += rm * rs;
    }
#pragma unroll
    for (int o = 16; o > 0; o >>= 1) part += __shfl_xor_sync(0xffffffffu, part, o);
    if (lane == 0) atomicAdd(&g_s[b], part);
}

// ---------------------------------------------------------------------------
// K4: dense4 = (view + I < sigmoid(s[b])) ? 1 : 0
// ---------------------------------------------------------------------------
__global__ void binarize_kernel(float* __restrict__ view) {
    size_t idx = (size_t)blockIdx.x * 256 + threadIdx.x;
    int b = (int)(idx >> 16);
    int ij = (int)(idx & 65535);
    int i = ij >> 8, j = ij & 255;
    float th = 1.f / (1.f + expf(-g_s[b]));
    float v = view[idx] + ((i == j) ? 1.f : 0.f);
    view[idx] = (v < th) ? 1.f : 0.f;
}

// ---------------------------------------------------------------------------
extern "C" void kernel_launch(void* const* d_in, const int* in_sizes, int n_in,
                              void* d_out, int out_size) {
    const float* X          = (const float*)d_in[0];
    const float* Aadj       = (const float*)d_in[1];
    const float* kernels    = (const float*)d_in[2];
    const float* biases     = (const float*)d_in[3];
    const float* attn_self  = (const float*)d_in[4];
    const float* attn_neigh = (const float*)d_in[5];
    const float* alpha      = (const float*)d_in[6];
    float* out  = (float*)d_out;            // [128,256,512]
    float* view = out + 16777216;           // dense4 region [128,256,256]

    const int ATTN_SMEM = 21152 * 4;  // 84608 B -> 2 CTAs/SM
    cudaFuncSetAttribute(attn_kernel, cudaFuncAttributeMaxDynamicSharedMemorySize, ATTN_SMEM);

    prep_kernel<<<1024, 256>>>(kernels, alpha);
    gemm_kernel<<<dim3(4, 256), 256>>>(X);
    asn_kernel<<<4096, 256>>>(attn_self, attn_neigh);
    attn_kernel<<<dim3(16, 128), 256, ATTN_SMEM>>>(Aadj, biases, out, view);
    binarize_kernel<<<32768, 256>>>(view);
}

// round 6
// speedup vs baseline: 1.6675x; 1.2041x over previous
#include <cuda_runtime.h>
#include <cuda_bf16.h>
#include <cstdint>

// ---------------------------------------------------------------------------
// GraphAttention: B=128, N=256, F=512, H=8, F_=64
// Output d_out: concat( output [128,256,512], dense4 [128,256,256] ) f32
// ---------------------------------------------------------------------------

__device__ float g_feats[16777216];            // [32768][512] fp32
__device__ float g_asn[524288];                // a_self [8][32768], a_neigh [8][32768]
__device__ float g_rowsum[128];
__device__ float g_s[128];
__device__ __nv_bfloat16 g_Xhi[16777216];      // X split-hi [32768][512]
__device__ __nv_bfloat16 g_Xlo[16777216];      // X split-lo
__device__ __nv_bfloat16 g_Whi[262144];        // W^T hi: [n=512][f=512]
__device__ __nv_bfloat16 g_Wlo[262144];        // W^T lo

// ---------------------------------------------------------------------------
// K0a: split X -> bf16 hi/lo
// ---------------------------------------------------------------------------
__global__ void convx_kernel(const float* __restrict__ X) {
    int idx = blockIdx.x * 256 + threadIdx.x;
    float v = X[idx];
    __nv_bfloat16 hi = __float2bfloat16(v);
    g_Xhi[idx] = hi;
    g_Xlo[idx] = __float2bfloat16(v - __bfloat162float(hi));
}

// ---------------------------------------------------------------------------
// K0b: W^T split to bf16 hi/lo (Wt[n][f] = kernels[n>>6][f][n&63]),
//      alpha row sums, zero g_s
// ---------------------------------------------------------------------------
__global__ void prep_kernel(const float* __restrict__ kernels,
                            const float* __restrict__ alpha) {
    int idx = blockIdx.x * 256 + threadIdx.x;
    if (idx < 262144) {
        int n = idx >> 9, f = idx & 511;
        int h = n >> 6, kk = n & 63;
        float v = kernels[(h * 512 + f) * 64 + kk];
        __nv_bfloat16 hi = __float2bfloat16(v);
        g_Whi[idx] = hi;
        g_Wlo[idx] = __float2bfloat16(v - __bfloat162float(hi));
    }
    if (idx < 128) {
        float s = 0.f;
        const float* ar = alpha + idx * 128;
#pragma unroll 4
        for (int k = 0; k < 128; ++k) s += ar[k];
        g_rowsum[idx] = s;
        g_s[idx] = 0.f;
    }
}

// ---------------------------------------------------------------------------
// K1: feats = X @ W via mma.sync bf16 split (hi*hi + hi*lo + lo*hi), f32 acc.
// CTA 128x128, BK=32, 8 warps (each 32x64). Padded smem rows (80B) ->
// conflict-free fragment loads. 40KB static smem, 2 CTAs/SM.
// ---------------------------------------------------------------------------
__device__ __forceinline__ void mma16816(float* c, uint32_t a0, uint32_t a1,
                                         uint32_t a2, uint32_t a3,
                                         uint32_t b0, uint32_t b1) {
    asm volatile(
        "mma.sync.aligned.m16n8k16.row.col.f32.bf16.bf16.f32 "
        "{%0,%1,%2,%3}, {%4,%5,%6,%7}, {%8,%9}, {%0,%1,%2,%3};"
        : "+f"(c[0]), "+f"(c[1]), "+f"(c[2]), "+f"(c[3])
        : "r"(a0), "r"(a1), "r"(a2), "r"(a3), "r"(b0), "r"(b1));
}

#define ROWB 80  // bytes per smem row (32 bf16 data + 8 pad)

__global__ __launch_bounds__(256, 2) void mma_gemm_kernel() {
    __shared__ __align__(16) char sAhi[128 * ROWB];
    __shared__ __align__(16) char sAlo[128 * ROWB];
    __shared__ __align__(16) char sBhi[128 * ROWB];
    __shared__ __align__(16) char sBlo[128 * ROWB];

    const int t = threadIdx.x;
    const int lane = t & 31, warp = t >> 5;
    const int warp_m = warp & 3;        // 4 x 32 rows
    const int warp_n = warp >> 2;       // 2 x 64 cols
    const int lr = lane >> 2, lc = lane & 3;
    const int bm = blockIdx.y * 128;
    const int bn = blockIdx.x * 128;

    float acc[2][8][4];
#pragma unroll
    for (int mi = 0; mi < 2; ++mi)
#pragma unroll
        for (int ni = 0; ni < 8; ++ni)
#pragma unroll
            for (int r = 0; r < 4; ++r) acc[mi][ni][r] = 0.f;

    for (int c = 0; c < 16; ++c) {
        const int k0 = c * 32;
        // ---- global -> smem: 4 tiles of [128][32] bf16 (512 uint4 each) ----
#pragma unroll
        for (int i = 0; i < 2; ++i) {
            int qq = t + 256 * i;          // 0..511
            int row = qq >> 2;             // 0..127
            int c16 = qq & 3;              // 16B chunk within row
            uint32_t soff = row * ROWB + c16 * 16;
            size_t ga = (size_t)(bm + row) * 512 + k0 + c16 * 8;
            size_t gb = (size_t)(bn + row) * 512 + k0 + c16 * 8;
            *(uint4*)(sAhi + soff) = *(const uint4*)(g_Xhi + ga);
            *(uint4*)(sAlo + soff) = *(const uint4*)(g_Xlo + ga);
            *(uint4*)(sBhi + soff) = *(const uint4*)(g_Whi + gb);
            *(uint4*)(sBlo + soff) = *(const uint4*)(g_Wlo + gb);
        }
        __syncthreads();

        // ---- compute: 2 k-steps of 16 ----
#pragma unroll
        for (int ks = 0; ks < 2; ++ks) {
            const uint32_t kb = (ks * 16 + lc * 2) * 2;  // byte offset of k pair
            uint32_t ahi[2][4], alo[2][4];
#pragma unroll
            for (int mi = 0; mi < 2; ++mi) {
                uint32_t ao = (warp_m * 32 + mi * 16 + lr) * ROWB + kb;
                ahi[mi][0] = *(const uint32_t*)(sAhi + ao);
                ahi[mi][1] = *(const uint32_t*)(sAhi + ao + 8 * ROWB);
                ahi[mi][2] = *(const uint32_t*)(sAhi + ao + 16);
                ahi[mi][3] = *(const uint32_t*)(sAhi + ao + 8 * ROWB + 16);
                alo[mi][0] = *(const uint32_t*)(sAlo + ao);
                alo[mi][1] = *(const uint32_t*)(sAlo + ao + 8 * ROWB);
                alo[mi][2] = *(const uint32_t*)(sAlo + ao + 16);
                alo[mi][3] = *(const uint32_t*)(sAlo + ao + 8 * ROWB + 16);
            }
#pragma unroll
            for (int g = 0; g < 2; ++g) {
                uint32_t bhi[4][2], blo[4][2];
#pragma unroll
                for (int nj = 0; nj < 4; ++nj) {
                    uint32_t bo = (warp_n * 64 + (g * 4 + nj) * 8 + lr) * ROWB + kb;
                    bhi[nj][0] = *(const uint32_t*)(sBhi + bo);
                    bhi[nj][1] = *(const uint32_t*)(sBhi + bo + 16);
                    blo[nj][0] = *(const uint32_t*)(sBlo + bo);
                    blo[nj][1] = *(const uint32_t*)(sBlo + bo + 16);
                }
#pragma unroll
                for (int mi = 0; mi < 2; ++mi)
#pragma unroll
                    for (int nj = 0; nj < 4; ++nj) {
                        float* a = acc[mi][g * 4 + nj];
                        mma16816(a, ahi[mi][0], ahi[mi][1], ahi[mi][2], ahi[mi][3],
                                 bhi[nj][0], bhi[nj][1]);
                        mma16816(a, ahi[mi][0], ahi[mi][1], ahi[mi][2], ahi[mi][3],
                                 blo[nj][0], blo[nj][1]);
                        mma16816(a, alo[mi][0], alo[mi][1], alo[mi][2], alo[mi][3],
                                 bhi[nj][0], bhi[nj][1]);
                    }
            }
        }
        __syncthreads();
    }

    // ---- epilogue: store fp32 accumulators ----
#pragma unroll
    for (int mi = 0; mi < 2; ++mi) {
        int row = bm + warp_m * 32 + mi * 16 + lr;
#pragma unroll
        for (int ni = 0; ni < 8; ++ni) {
            int col = bn + warp_n * 64 + ni * 8 + lc * 2;
            *(float2*)(g_feats + (size_t)row * 512 + col) =
                make_float2(acc[mi][ni][0], acc[mi][ni][1]);
            *(float2*)(g_feats + (size_t)(row + 8) * 512 + col) =
                make_float2(acc[mi][ni][2], acc[mi][ni][3]);
        }
    }
}

// ---------------------------------------------------------------------------
// K2: a_self / a_neigh dot products
// ---------------------------------------------------------------------------
__global__ void asn_kernel(const float* __restrict__ attn_self,
                           const float* __restrict__ attn_neigh) {
    __shared__ float sr[4096];
    __shared__ float ss[512], sn[512];
    int t = threadIdx.x;
    for (int u = t; u < 512; u += 256) { ss[u] = attn_self[u]; sn[u] = attn_neigh[u]; }
    size_t base = (size_t)blockIdx.x * 4096;
    for (int u = t; u < 4096; u += 256) sr[u] = g_feats[base + u];
    __syncthreads();

    int warp = t >> 5, lane = t & 31;
    int h = lane >> 2, kb = (lane & 3) << 4;
    const float* fr = sr + warp * 512;
    int off = h * 64 + kb;
    float ps = 0.f, pn = 0.f;
#pragma unroll
    for (int u = 0; u < 16; ++u) {
        float fv = fr[off + u];
        ps += fv * ss[off + u];
        pn += fv * sn[off + u];
    }
    ps += __shfl_xor_sync(0xffffffffu, ps, 1);
    ps += __shfl_xor_sync(0xffffffffu, ps, 2);
    pn += __shfl_xor_sync(0xffffffffu, pn, 1);
    pn += __shfl_xor_sync(0xffffffffu, pn, 2);
    if ((lane & 3) == 0) {
        int row = blockIdx.x * 8 + warp;
        g_asn[h * 32768 + row] = ps;
        g_asn[262144 + h * 32768 + row] = pn;
    }
}

// ---------------------------------------------------------------------------
// K3: fused attention: 16-row tiles, 2 CTAs/SM (unchanged from R4 pass).
// ---------------------------------------------------------------------------
__global__ __launch_bounds__(256, 2) void attn_kernel(
    const float* __restrict__ Aadj, const float* __restrict__ biases,
    float* __restrict__ out, float* __restrict__ view) {
    extern __shared__ float sm[];
    float* sfeat = sm;              // 16384 f
    float* sw    = sm + 16384;      // 4096 f
    float* sbias = sm + 20480;      // 512 f
    float* ssel  = sm + 20992;      // 16 f
    float* sred  = sm + 21008;      // 128 f
    float* sinv  = sm + 21136;      // 16 f
    float4* sf4 = (float4*)sfeat;

    const int b = blockIdx.y;
    const int i0 = blockIdx.x * 16;
    const int t = threadIdx.x;
    const int lane = t & 31, warp = t >> 5;
    const int kq = t & 15, jg = (t >> 4) & 7, ih = t >> 7;
    const int rbase = ih * 8;

    unsigned amask = 0u;
#pragma unroll
    for (int i = 0; i < 16; ++i)
        amask |= (Aadj[((size_t)b * 256 + i0 + i) * 256 + t] > 0.5f) ? (1u << i) : 0u;
    for (int u = t; u < 512; u += 256) sbias[u] = biases[u];

    float vacc[16];
#pragma unroll
    for (int i = 0; i < 16; ++i) vacc[i] = 0.f;

    for (int h = 0; h < 8; ++h) {
        const float* fb = g_feats + (size_t)b * 256 * 512 + h * 64;
        for (int u = t; u < 4096; u += 256) {
            int j = u >> 4, c = u & 15;
            sf4[u] = *(const float4*)(fb + (size_t)j * 512 + c * 4);
        }
        if (t < 16) ssel[t] = g_asn[h * 32768 + b * 256 + i0 + t];
        float an = g_asn[262144 + h * 32768 + b * 256 + t];
        __syncthreads();

        float w[16];
#pragma unroll
        for (int i = 0; i < 16; ++i) {
            float z = ssel[i] + an;
            z = (z > 0.f) ? z : 0.2f * z;
            w[i] = ((amask >> i) & 1u) ? __expf(z) : 0.f;
        }
#pragma unroll
        for (int i = 0; i < 16; ++i) {
            float v = w[i];
#pragma unroll
            for (int o = 16; o > 0; o >>= 1) v += __shfl_xor_sync(0xffffffffu, v, o);
            if (lane == 0) sred[i * 8 + warp] = v;
        }
        __syncthreads();
        if (t < 16) {
            float s = 0.f;
#pragma unroll
            for (int g = 0; g < 8; ++g) s += sred[t * 8 + g];
            sinv[t] = 1.f / s;
        }
        __syncthreads();
#pragma unroll
        for (int i = 0; i < 16; ++i) {
            float a = w[i] * sinv[i];
            sw[i * 256 + t] = a;
            vacc[i] += 0.125f * a;
        }
        __syncthreads();

        float4 acc[8];
#pragma unroll
        for (int r = 0; r < 8; ++r) acc[r] = make_float4(0.f, 0.f, 0.f, 0.f);
#pragma unroll 4
        for (int s = 0; s < 32; ++s) {
            int j = jg * 32 + s;
            float4 f = sf4[j * 16 + kq];
#pragma unroll
            for (int r = 0; r < 8; ++r) {
                float wv = sw[(rbase + r) * 256 + j];
                acc[r].x += wv * f.x; acc[r].y += wv * f.y;
                acc[r].z += wv * f.z; acc[r].w += wv * f.w;
            }
        }
        __syncthreads();
#pragma unroll
        for (int r = 0; r < 8; ++r) sf4[(jg * 16 + rbase + r) * 16 + kq] = acc[r];
        __syncthreads();
#pragma unroll
        for (int rr = 0; rr < 4; ++rr) {
            int o = t + 256 * rr;
            int i = o >> 6, k = o & 63;
            float s = 0.f;
#pragma unroll
            for (int g = 0; g < 8; ++g) s += sfeat[(g * 16 + i) * 64 + k];
            s += sbias[h * 64 + k];
            out[((size_t)b * 256 + i0 + i) * 512 + h * 64 + k] = fmaxf(s, 0.f);
        }
        __syncthreads();
    }

#pragma unroll
    for (int i = 0; i < 16; ++i)
        view[((size_t)b * 256 + i0 + i) * 256 + t] = vacc[i];

    float part = 0.f;
    float rs = g_rowsum[t >> 1];
#pragma unroll
    for (int pi = 0; pi < 8; ++pi) {
        float rm = fmaxf(vacc[2 * pi], vacc[2 * pi + 1]);
        rm = fmaxf(rm, __shfl_xor_sync(0xffffffffu, rm, 1));
        if (!(t & 1)) part += rm * rs;
    }
#pragma unroll
    for (int o = 16; o > 0; o >>= 1) part += __shfl_xor_sync(0xffffffffu, part, o);
    if (lane == 0) atomicAdd(&g_s[b], part);
}

// ---------------------------------------------------------------------------
// K4: dense4 = (view + I < sigmoid(s[b])) ? 1 : 0
// ---------------------------------------------------------------------------
__global__ void binarize_kernel(float* __restrict__ view) {
    size_t idx = (size_t)blockIdx.x * 256 + threadIdx.x;
    int b = (int)(idx >> 16);
    int ij = (int)(idx & 65535);
    int i = ij >> 8, j = ij & 255;
    float th = 1.f / (1.f + expf(-g_s[b]));
    float v = view[idx] + ((i == j) ? 1.f : 0.f);
    view[idx] = (v < th) ? 1.f : 0.f;
}

// ---------------------------------------------------------------------------
extern "C" void kernel_launch(void* const* d_in, const int* in_sizes, int n_in,
                              void* d_out, int out_size) {
    const float* X          = (const float*)d_in[0];
    const float* Aadj       = (const float*)d_in[1];
    const float* kernels    = (const float*)d_in[2];
    const float* biases     = (const float*)d_in[3];
    const float* attn_self  = (const float*)d_in[4];
    const float* attn_neigh = (const float*)d_in[5];
    const float* alpha      = (const float*)d_in[6];
    float* out  = (float*)d_out;            // [128,256,512]
    float* view = out + 16777216;           // dense4 region [128,256,256]

    const int ATTN_SMEM = 21152 * 4;  // 84608 B -> 2 CTAs/SM
    cudaFuncSetAttribute(attn_kernel, cudaFuncAttributeMaxDynamicSharedMemorySize, ATTN_SMEM);

    convx_kernel<<<65536, 256>>>(X);
    prep_kernel<<<1024, 256>>>(kernels, alpha);
    mma_gemm_kernel<<<dim3(4, 256), 256>>>();
    asn_kernel<<<4096, 256>>>(attn_self, attn_neigh);
    attn_kernel<<<dim3(16, 128), 256, ATTN_SMEM>>>(Aadj, biases, out, view);
    binarize_kernel<<<32768, 256>>>(view);
}

// round 7
// speedup vs baseline: 2.0759x; 1.2449x over previous
#include <cuda_runtime.h>
#include <cuda_bf16.h>
#include <cstdint>

// ---------------------------------------------------------------------------
// GraphAttention: B=128, N=256, F=512, H=8, F_=64
// Output d_out: concat( output [128,256,512], dense4 [128,256,256] ) f32
// ---------------------------------------------------------------------------

__device__ float g_asn[524288];                // a_self [8][32768], a_neigh [8][32768]
__device__ float g_rowsum[128];
__device__ float g_s[128];
__device__ __nv_bfloat16 g_Xhi[16777216];      // X split-hi [32768][512]
__device__ __nv_bfloat16 g_Xlo[16777216];      // X split-lo
__device__ __nv_bfloat16 g_Whi[262144];        // W^T hi: [n=512][f=512]
__device__ __nv_bfloat16 g_Wlo[262144];        // W^T lo
__device__ __nv_bfloat16 g_fhi[16777216];      // feats hi [32768][512]
__device__ __nv_bfloat16 g_flo[16777216];      // feats lo

__device__ __forceinline__ uint32_t smem_u32(const void* p) {
    uint32_t a;
    asm("{ .reg .u64 t; cvta.to.shared.u64 t, %1; cvt.u32.u64 %0, t; }" : "=r"(a) : "l"(p));
    return a;
}
__device__ __forceinline__ void mma16816(float* c, uint32_t a0, uint32_t a1,
                                         uint32_t a2, uint32_t a3,
                                         uint32_t b0, uint32_t b1) {
    asm volatile(
        "mma.sync.aligned.m16n8k16.row.col.f32.bf16.bf16.f32 "
        "{%0,%1,%2,%3}, {%4,%5,%6,%7}, {%8,%9}, {%0,%1,%2,%3};"
        : "+f"(c[0]), "+f"(c[1]), "+f"(c[2]), "+f"(c[3])
        : "r"(a0), "r"(a1), "r"(a2), "r"(a3), "r"(b0), "r"(b1));
}
__device__ __forceinline__ void ldsm_x2_t(uint32_t& r0, uint32_t& r1, uint32_t addr) {
    asm volatile("ldmatrix.sync.aligned.m8n8.x2.trans.shared.b16 {%0,%1}, [%2];"
                 : "=r"(r0), "=r"(r1) : "r"(addr));
}

// ---------------------------------------------------------------------------
// K0a: split X -> bf16 hi/lo
// ---------------------------------------------------------------------------
__global__ void convx_kernel(const float* __restrict__ X) {
    int idx = blockIdx.x * 256 + threadIdx.x;
    float v = X[idx];
    __nv_bfloat16 hi = __float2bfloat16(v);
    g_Xhi[idx] = hi;
    g_Xlo[idx] = __float2bfloat16(v - __bfloat162float(hi));
}

// ---------------------------------------------------------------------------
// K0b: W^T split to bf16 hi/lo, alpha row sums, zero g_s
// ---------------------------------------------------------------------------
__global__ void prep_kernel(const float* __restrict__ kernels,
                            const float* __restrict__ alpha) {
    int idx = blockIdx.x * 256 + threadIdx.x;
    if (idx < 262144) {
        int n = idx >> 9, f = idx & 511;
        int h = n >> 6, kk = n & 63;
        float v = kernels[(h * 512 + f) * 64 + kk];
        __nv_bfloat16 hi = __float2bfloat16(v);
        g_Whi[idx] = hi;
        g_Wlo[idx] = __float2bfloat16(v - __bfloat162float(hi));
    }
    if (idx < 128) {
        float s = 0.f;
        const float* ar = alpha + idx * 128;
#pragma unroll 4
        for (int k = 0; k < 128; ++k) s += ar[k];
        g_rowsum[idx] = s;
        g_s[idx] = 0.f;
    }
}

// ---------------------------------------------------------------------------
// K1: feats = X @ W via mma.sync bf16 split. Epilogue writes feats hi/lo
// bf16 AND computes a_self/a_neigh inline (each warp = one head's 64 cols).
// ---------------------------------------------------------------------------
#define ROWB 80  // bytes per smem row (32 bf16 data + 8 pad)

__global__ __launch_bounds__(256, 2) void mma_gemm_kernel(
    const float* __restrict__ attn_self, const float* __restrict__ attn_neigh) {
    __shared__ __align__(16) char sAhi[128 * ROWB];
    __shared__ __align__(16) char sAlo[128 * ROWB];
    __shared__ __align__(16) char sBhi[128 * ROWB];
    __shared__ __align__(16) char sBlo[128 * ROWB];
    __shared__ float s_self[512], s_neigh[512];

    const int t = threadIdx.x;
    const int lane = t & 31, warp = t >> 5;
    const int warp_m = warp & 3;
    const int warp_n = warp >> 2;
    const int lr = lane >> 2, lc = lane & 3;
    const int bm = blockIdx.y * 128;
    const int bn = blockIdx.x * 128;

    for (int u = t; u < 512; u += 256) { s_self[u] = attn_self[u]; s_neigh[u] = attn_neigh[u]; }

    float acc[2][8][4];
#pragma unroll
    for (int mi = 0; mi < 2; ++mi)
#pragma unroll
        for (int ni = 0; ni < 8; ++ni)
#pragma unroll
            for (int r = 0; r < 4; ++r) acc[mi][ni][r] = 0.f;

    for (int c = 0; c < 16; ++c) {
        const int k0 = c * 32;
#pragma unroll
        for (int i = 0; i < 2; ++i) {
            int qq = t + 256 * i;
            int row = qq >> 2;
            int c16 = qq & 3;
            uint32_t soff = row * ROWB + c16 * 16;
            size_t ga = (size_t)(bm + row) * 512 + k0 + c16 * 8;
            size_t gb = (size_t)(bn + row) * 512 + k0 + c16 * 8;
            *(uint4*)(sAhi + soff) = *(const uint4*)(g_Xhi + ga);
            *(uint4*)(sAlo + soff) = *(const uint4*)(g_Xlo + ga);
            *(uint4*)(sBhi + soff) = *(const uint4*)(g_Whi + gb);
            *(uint4*)(sBlo + soff) = *(const uint4*)(g_Wlo + gb);
        }
        __syncthreads();

#pragma unroll
        for (int ks = 0; ks < 2; ++ks) {
            const uint32_t kb = (ks * 16 + lc * 2) * 2;
            uint32_t ahi[2][4], alo[2][4];
#pragma unroll
            for (int mi = 0; mi < 2; ++mi) {
                uint32_t ao = (warp_m * 32 + mi * 16 + lr) * ROWB + kb;
                ahi[mi][0] = *(const uint32_t*)(sAhi + ao);
                ahi[mi][1] = *(const uint32_t*)(sAhi + ao + 8 * ROWB);
                ahi[mi][2] = *(const uint32_t*)(sAhi + ao + 16);
                ahi[mi][3] = *(const uint32_t*)(sAhi + ao + 8 * ROWB + 16);
                alo[mi][0] = *(const uint32_t*)(sAlo + ao);
                alo[mi][1] = *(const uint32_t*)(sAlo + ao + 8 * ROWB);
                alo[mi][2] = *(const uint32_t*)(sAlo + ao + 16);
                alo[mi][3] = *(const uint32_t*)(sAlo + ao + 8 * ROWB + 16);
            }
#pragma unroll
            for (int g = 0; g < 2; ++g) {
                uint32_t bhi[4][2], blo[4][2];
#pragma unroll
                for (int nj = 0; nj < 4; ++nj) {
                    uint32_t bo = (warp_n * 64 + (g * 4 + nj) * 8 + lr) * ROWB + kb;
                    bhi[nj][0] = *(const uint32_t*)(sBhi + bo);
                    bhi[nj][1] = *(const uint32_t*)(sBhi + bo + 16);
                    blo[nj][0] = *(const uint32_t*)(sBlo + bo);
                    blo[nj][1] = *(const uint32_t*)(sBlo + bo + 16);
                }
#pragma unroll
                for (int mi = 0; mi < 2; ++mi)
#pragma unroll
                    for (int nj = 0; nj < 4; ++nj) {
                        float* a = acc[mi][g * 4 + nj];
                        mma16816(a, ahi[mi][0], ahi[mi][1], ahi[mi][2], ahi[mi][3],
                                 bhi[nj][0], bhi[nj][1]);
                        mma16816(a, ahi[mi][0], ahi[mi][1], ahi[mi][2], ahi[mi][3],
                                 blo[nj][0], blo[nj][1]);
                        mma16816(a, alo[mi][0], alo[mi][1], alo[mi][2], alo[mi][3],
                                 bhi[nj][0], bhi[nj][1]);
                    }
            }
        }
        __syncthreads();
    }

    // ---- epilogue: feats hi/lo bf16 stores + inline a_self/a_neigh ----
    const int hh = (bn >> 6) + warp_n;   // this warp's head
    float ps0[2] = {0.f, 0.f}, ps1[2] = {0.f, 0.f};
    float pn0[2] = {0.f, 0.f}, pn1[2] = {0.f, 0.f};
#pragma unroll
    for (int mi = 0; mi < 2; ++mi) {
        int row = bm + warp_m * 32 + mi * 16 + lr;
#pragma unroll
        for (int ni = 0; ni < 8; ++ni) {
            int col = bn + warp_n * 64 + ni * 8 + lc * 2;
            float v0 = acc[mi][ni][0], v1 = acc[mi][ni][1];
            float v2 = acc[mi][ni][2], v3 = acc[mi][ni][3];
            __nv_bfloat16 h0 = __float2bfloat16(v0), h1 = __float2bfloat16(v1);
            __nv_bfloat16 h2 = __float2bfloat16(v2), h3 = __float2bfloat16(v3);
            *(__nv_bfloat162*)(g_fhi + (size_t)row * 512 + col) =
                __nv_bfloat162(h0, h1);
            *(__nv_bfloat162*)(g_fhi + (size_t)(row + 8) * 512 + col) =
                __nv_bfloat162(h2, h3);
            *(__nv_bfloat162*)(g_flo + (size_t)row * 512 + col) = __nv_bfloat162(
                __float2bfloat16(v0 - __bfloat162float(h0)),
                __float2bfloat16(v1 - __bfloat162float(h1)));
            *(__nv_bfloat162*)(g_flo + (size_t)(row + 8) * 512 + col) = __nv_bfloat162(
                __float2bfloat16(v2 - __bfloat162float(h2)),
                __float2bfloat16(v3 - __bfloat162float(h3)));
            float s0 = s_self[col], s1 = s_self[col + 1];
            float q0 = s_neigh[col], q1 = s_neigh[col + 1];
            ps0[mi] += v0 * s0 + v1 * s1;
            ps1[mi] += v2 * s0 + v3 * s1;
            pn0[mi] += v0 * q0 + v1 * q1;
            pn1[mi] += v2 * q0 + v3 * q1;
        }
    }
#pragma unroll
    for (int mi = 0; mi < 2; ++mi) {
        float a0 = ps0[mi], a1 = ps1[mi], c0 = pn0[mi], c1 = pn1[mi];
        a0 += __shfl_xor_sync(0xffffffffu, a0, 1); a0 += __shfl_xor_sync(0xffffffffu, a0, 2);
        a1 += __shfl_xor_sync(0xffffffffu, a1, 1); a1 += __shfl_xor_sync(0xffffffffu, a1, 2);
        c0 += __shfl_xor_sync(0xffffffffu, c0, 1); c0 += __shfl_xor_sync(0xffffffffu, c0, 2);
        c1 += __shfl_xor_sync(0xffffffffu, c1, 1); c1 += __shfl_xor_sync(0xffffffffu, c1, 2);
        if (lc == 0) {
            int row = bm + warp_m * 32 + mi * 16 + lr;
            g_asn[hh * 32768 + row] = a0;
            g_asn[hh * 32768 + row + 8] = a1;
            g_asn[262144 + hh * 32768 + row] = c0;
            g_asn[262144 + hh * 32768 + row + 8] = c1;
        }
    }
}

// ---------------------------------------------------------------------------
// K3: fused attention v3. Aggregation via mma.sync bf16 split (w_hi*f_hi +
// w_hi*f_lo + w_lo*f_hi). 16-row i-tiles, 2 CTAs/SM, ~83 KB dynamic smem.
// ---------------------------------------------------------------------------
#define AT_SFHI 0          // 32768: feats hi [256][64] bf16, XOR-swizzled
#define AT_SFLO 32768      // 32768: feats lo
#define AT_SWHI 65536      // 8448: attn hi [16][264] bf16 (528B rows)
#define AT_SWLO 73984      // 8448: attn lo
#define AT_SSEL 82432      // 64
#define AT_SRED 82496      // 512
#define AT_SINV 83008      // 64
#define AT_SIZE 83072

__global__ __launch_bounds__(256, 2) void attn_kernel(
    const float* __restrict__ Aadj, const float* __restrict__ biases,
    float* __restrict__ out, float* __restrict__ view) {
    extern __shared__ char smc[];
    const uint32_t sbase = smem_u32(smc);
    float* ssel = (float*)(smc + AT_SSEL);
    float* sred = (float*)(smc + AT_SRED);
    float* sinv = (float*)(smc + AT_SINV);

    const int b = blockIdx.y;
    const int i0 = blockIdx.x * 16;
    const int t = threadIdx.x;
    const int lane = t & 31, warp = t >> 5;
    const int gid = lane >> 2, tig = lane & 3;

    unsigned amask = 0u;
#pragma unroll
    for (int i = 0; i < 16; ++i)
        amask |= (Aadj[((size_t)b * 256 + i0 + i) * 256 + t] > 0.5f) ? (1u << i) : 0u;

    float vacc[16];
#pragma unroll
    for (int i = 0; i < 16; ++i) vacc[i] = 0.f;

    for (int h = 0; h < 8; ++h) {
        // --- feats hi/lo -> swizzled smem ([j][64] bf16, 128B rows) ---
#pragma unroll
        for (int i = 0; i < 8; ++i) {
            int q = t + 256 * i;           // 0..2047
            int j = q >> 3, c = q & 7;
            uint32_t so = j * 128 + ((c ^ (j & 7)) * 16);
            size_t g = (size_t)(b * 256 + j) * 512 + h * 64 + c * 8;
            *(uint4*)(smc + AT_SFHI + so) = *(const uint4*)(g_fhi + g);
            *(uint4*)(smc + AT_SFLO + so) = *(const uint4*)(g_flo + g);
        }
        if (t < 16) ssel[t] = g_asn[h * 32768 + b * 256 + i0 + t];
        float an = g_asn[262144 + h * 32768 + b * 256 + t];
        __syncthreads();

        // --- logits + exp (thread t = column j=t, 16 rows) ---
        float w[16];
#pragma unroll
        for (int i = 0; i < 16; ++i) {
            float z = ssel[i] + an;
            z = (z > 0.f) ? z : 0.2f * z;
            w[i] = ((amask >> i) & 1u) ? __expf(z) : 0.f;
        }
#pragma unroll
        for (int i = 0; i < 16; ++i) {
            float v = w[i];
#pragma unroll
            for (int o = 16; o > 0; o >>= 1) v += __shfl_xor_sync(0xffffffffu, v, o);
            if (lane == 0) sred[i * 8 + warp] = v;
        }
        __syncthreads();
        if (t < 16) {
            float s = 0.f;
#pragma unroll
            for (int g = 0; g < 8; ++g) s += sred[t * 8 + g];
            sinv[t] = 1.f / s;
        }
        __syncthreads();
#pragma unroll
        for (int i = 0; i < 16; ++i) {
            float a = w[i] * sinv[i];
            vacc[i] += 0.125f * a;
            __nv_bfloat16 ah = __float2bfloat16(a);
            *(__nv_bfloat16*)(smc + AT_SWHI + i * 528 + t * 2) = ah;
            *(__nv_bfloat16*)(smc + AT_SWLO + i * 528 + t * 2) =
                __float2bfloat16(a - __bfloat162float(ah));
        }
        __syncthreads();

        // --- node = attn @ feats via mma: warp owns n-tile of 8, full K=256 ---
        float acc[4] = {0.f, 0.f, 0.f, 0.f};
#pragma unroll
        for (int ks = 0; ks < 16; ++ks) {
            const int k0 = ks * 16;
            uint32_t ao = (uint32_t)(gid * 528 + k0 * 2 + tig * 4);
            uint32_t ah0 = *(const uint32_t*)(smc + AT_SWHI + ao);
            uint32_t ah1 = *(const uint32_t*)(smc + AT_SWHI + ao + 8 * 528);
            uint32_t ah2 = *(const uint32_t*)(smc + AT_SWHI + ao + 16);
            uint32_t ah3 = *(const uint32_t*)(smc + AT_SWHI + ao + 8 * 528 + 16);
            uint32_t al0 = *(const uint32_t*)(smc + AT_SWLO + ao);
            uint32_t al1 = *(const uint32_t*)(smc + AT_SWLO + ao + 8 * 528);
            uint32_t al2 = *(const uint32_t*)(smc + AT_SWLO + ao + 16);
            uint32_t al3 = *(const uint32_t*)(smc + AT_SWLO + ao + 8 * 528 + 16);
            int r = k0 + (lane & 15);
            uint32_t boff = (uint32_t)(r * 128 + ((warp ^ (r & 7)) * 16));
            uint32_t bh0, bh1, bl0, bl1;
            ldsm_x2_t(bh0, bh1, sbase + AT_SFHI + boff);
            ldsm_x2_t(bl0, bl1, sbase + AT_SFLO + boff);
            mma16816(acc, ah0, ah1, ah2, ah3, bh0, bh1);
            mma16816(acc, ah0, ah1, ah2, ah3, bl0, bl1);
            mma16816(acc, al0, al1, al2, al3, bh0, bh1);
        }
        // --- epilogue: bias + relu + direct store ---
        {
            int col = h * 64 + warp * 8 + tig * 2;
            float b0 = biases[col], b1 = biases[col + 1];
            float* o0 = out + (size_t)(b * 256 + i0 + gid) * 512 + col;
            *(float2*)o0 = make_float2(fmaxf(acc[0] + b0, 0.f), fmaxf(acc[1] + b1, 0.f));
            float* o1 = o0 + 8 * 512;
            *(float2*)o1 = make_float2(fmaxf(acc[2] + b0, 0.f), fmaxf(acc[3] + b1, 0.f));
        }
        __syncthreads();
    }

    // --- view store ---
#pragma unroll
    for (int i = 0; i < 16; ++i)
        view[((size_t)b * 256 + i0 + i) * 256 + t] = vacc[i];

    // --- 2x2 max pool + s[b] partial ---
    float part = 0.f;
    float rs = g_rowsum[t >> 1];
#pragma unroll
    for (int pi = 0; pi < 8; ++pi) {
        float rm = fmaxf(vacc[2 * pi], vacc[2 * pi + 1]);
        rm = fmaxf(rm, __shfl_xor_sync(0xffffffffu, rm, 1));
        if (!(t & 1)) part += rm * rs;
    }
#pragma unroll
    for (int o = 16; o > 0; o >>= 1) part += __shfl_xor_sync(0xffffffffu, part, o);
    if (lane == 0) atomicAdd(&g_s[b], part);
}

// ---------------------------------------------------------------------------
// K4: dense4 = (view + I < sigmoid(s[b])) ? 1 : 0
// ---------------------------------------------------------------------------
__global__ void binarize_kernel(float* __restrict__ view) {
    size_t idx = (size_t)blockIdx.x * 256 + threadIdx.x;
    int b = (int)(idx >> 16);
    int ij = (int)(idx & 65535);
    int i = ij >> 8, j = ij & 255;
    float th = 1.f / (1.f + expf(-g_s[b]));
    float v = view[idx] + ((i == j) ? 1.f : 0.f);
    view[idx] = (v < th) ? 1.f : 0.f;
}

// ---------------------------------------------------------------------------
extern "C" void kernel_launch(void* const* d_in, const int* in_sizes, int n_in,
                              void* d_out, int out_size) {
    const float* X          = (const float*)d_in[0];
    const float* Aadj       = (const float*)d_in[1];
    const float* kernels    = (const float*)d_in[2];
    const float* biases     = (const float*)d_in[3];
    const float* attn_self  = (const float*)d_in[4];
    const float* attn_neigh = (const float*)d_in[5];
    const float* alpha      = (const float*)d_in[6];
    float* out  = (float*)d_out;            // [128,256,512]
    float* view = out + 16777216;           // dense4 region [128,256,256]

    cudaFuncSetAttribute(attn_kernel, cudaFuncAttributeMaxDynamicSharedMemorySize, AT_SIZE);

    convx_kernel<<<65536, 256>>>(X);
    prep_kernel<<<1024, 256>>>(kernels, alpha);
    mma_gemm_kernel<<<dim3(4, 256), 256>>>(attn_self, attn_neigh);
    attn_kernel<<<dim3(16, 128), 256, AT_SIZE>>>(Aadj, biases, out, view);
    binarize_kernel<<<32768, 256>>>(view);
}

// round 9
// speedup vs baseline: 2.1858x; 1.0529x over previous
#include <cuda_runtime.h>
#include <cuda_bf16.h>
#include <cstdint>

// ---------------------------------------------------------------------------
// GraphAttention: B=128, N=256, F=512, H=8, F_=64
// Output d_out: concat( output [128,256,512], dense4 [128,256,256] ) f32
// ---------------------------------------------------------------------------

__device__ float g_asn[524288];                // a_self [8][32768], a_neigh [8][32768]
__device__ float g_rowsum[128];
__device__ float g_s[128];
__device__ __nv_bfloat16 g_Xhi[16777216];      // X split-hi [32768][512]
__device__ __nv_bfloat16 g_Xlo[16777216];      // X split-lo
__device__ __nv_bfloat16 g_Whi[262144];        // W^T hi: [n=512][f=512]
__device__ __nv_bfloat16 g_Wlo[262144];        // W^T lo
__device__ __nv_bfloat16 g_fhi[16777216];      // feats hi [32768][512]
__device__ __nv_bfloat16 g_flo[16777216];      // feats lo

__device__ __forceinline__ uint32_t smem_u32(const void* p) {
    uint32_t a;
    asm("{ .reg .u64 t; cvta.to.shared.u64 t, %1; cvt.u32.u64 %0, t; }" : "=r"(a) : "l"(p));
    return a;
}
__device__ __forceinline__ void mma16816(float* c, uint32_t a0, uint32_t a1,
                                         uint32_t a2, uint32_t a3,
                                         uint32_t b0, uint32_t b1) {
    asm volatile(
        "mma.sync.aligned.m16n8k16.row.col.f32.bf16.bf16.f32 "
        "{%0,%1,%2,%3}, {%4,%5,%6,%7}, {%8,%9}, {%0,%1,%2,%3};"
        : "+f"(c[0]), "+f"(c[1]), "+f"(c[2]), "+f"(c[3])
        : "r"(a0), "r"(a1), "r"(a2), "r"(a3), "r"(b0), "r"(b1));
}
__device__ __forceinline__ void ldsm_x4(uint32_t* r, uint32_t addr) {
    asm volatile("ldmatrix.sync.aligned.m8n8.x4.shared.b16 {%0,%1,%2,%3}, [%4];"
                 : "=r"(r[0]), "=r"(r[1]), "=r"(r[2]), "=r"(r[3]) : "r"(addr));
}
__device__ __forceinline__ void ldsm_x4_t(uint32_t* r, uint32_t addr) {
    asm volatile("ldmatrix.sync.aligned.m8n8.x4.trans.shared.b16 {%0,%1,%2,%3}, [%4];"
                 : "=r"(r[0]), "=r"(r[1]), "=r"(r[2]), "=r"(r[3]) : "r"(addr));
}

// ---------------------------------------------------------------------------
// K0a: split X -> bf16 hi/lo
// ---------------------------------------------------------------------------
__global__ void convx_kernel(const float* __restrict__ X) {
    int idx = blockIdx.x * 256 + threadIdx.x;
    float v = X[idx];
    __nv_bfloat16 hi = __float2bfloat16(v);
    g_Xhi[idx] = hi;
    g_Xlo[idx] = __float2bfloat16(v - __bfloat162float(hi));
}

// ---------------------------------------------------------------------------
// K0b: W^T split to bf16 hi/lo, alpha row sums, zero g_s
// ---------------------------------------------------------------------------
__global__ void prep_kernel(const float* __restrict__ kernels,
                            const float* __restrict__ alpha) {
    int idx = blockIdx.x * 256 + threadIdx.x;
    if (idx < 262144) {
        int n = idx >> 9, f = idx & 511;
        int h = n >> 6, kk = n & 63;
        float v = kernels[(h * 512 + f) * 64 + kk];
        __nv_bfloat16 hi = __float2bfloat16(v);
        g_Whi[idx] = hi;
        g_Wlo[idx] = __float2bfloat16(v - __bfloat162float(hi));
    }
    if (idx < 128) {
        float s = 0.f;
        const float* ar = alpha + idx * 128;
#pragma unroll 4
        for (int k = 0; k < 128; ++k) s += ar[k];
        g_rowsum[idx] = s;
        g_s[idx] = 0.f;
    }
}

// ---------------------------------------------------------------------------
// K1: feats = X @ W via mma.sync bf16 split, ldmatrix.x4 fragment loads.
// ---------------------------------------------------------------------------
#define ROWB 80  // bytes per smem row (32 bf16 data + 8 pad)

__global__ __launch_bounds__(256, 2) void mma_gemm_kernel(
    const float* __restrict__ attn_self, const float* __restrict__ attn_neigh) {
    __shared__ __align__(16) char sAhi[128 * ROWB];
    __shared__ __align__(16) char sAlo[128 * ROWB];
    __shared__ __align__(16) char sBhi[128 * ROWB];
    __shared__ __align__(16) char sBlo[128 * ROWB];
    __shared__ float s_self[512], s_neigh[512];

    const int t = threadIdx.x;
    const int lane = t & 31, warp = t >> 5;
    const int warp_m = warp & 3;
    const int warp_n = warp >> 2;
    const int lr = lane >> 2, lc = lane & 3;
    const int bm = blockIdx.y * 128;
    const int bn = blockIdx.x * 128;
    const uint32_t uAhi = smem_u32(sAhi), uAlo = smem_u32(sAlo);
    const uint32_t uBhi = smem_u32(sBhi), uBlo = smem_u32(sBlo);

    for (int u = t; u < 512; u += 256) { s_self[u] = attn_self[u]; s_neigh[u] = attn_neigh[u]; }

    float acc[2][8][4];
#pragma unroll
    for (int mi = 0; mi < 2; ++mi)
#pragma unroll
        for (int ni = 0; ni < 8; ++ni)
#pragma unroll
            for (int r = 0; r < 4; ++r) acc[mi][ni][r] = 0.f;

    // precomputed ldmatrix per-lane offsets
    const uint32_t a_lo = (uint32_t)((lane & 15) * ROWB + ((lane >> 4) << 4));
    const uint32_t b_lo = (uint32_t)((((lane >> 4) << 3) + (lane & 7)) * ROWB +
                                     (((lane >> 3) & 1) << 4));

    for (int c = 0; c < 16; ++c) {
        const int k0 = c * 32;
#pragma unroll
        for (int i = 0; i < 2; ++i) {
            int qq = t + 256 * i;
            int row = qq >> 2;
            int c16 = qq & 3;
            uint32_t soff = row * ROWB + c16 * 16;
            size_t ga = (size_t)(bm + row) * 512 + k0 + c16 * 8;
            size_t gb = (size_t)(bn + row) * 512 + k0 + c16 * 8;
            *(uint4*)(sAhi + soff) = *(const uint4*)(g_Xhi + ga);
            *(uint4*)(sAlo + soff) = *(const uint4*)(g_Xlo + ga);
            *(uint4*)(sBhi + soff) = *(const uint4*)(g_Whi + gb);
            *(uint4*)(sBlo + soff) = *(const uint4*)(g_Wlo + gb);
        }
        __syncthreads();

#pragma unroll
        for (int ks = 0; ks < 2; ++ks) {
            uint32_t ahi[2][4], alo[2][4];
#pragma unroll
            for (int mi = 0; mi < 2; ++mi) {
                uint32_t ao = (uint32_t)((warp_m * 32 + mi * 16) * ROWB + ks * 32) + a_lo;
                ldsm_x4(ahi[mi], uAhi + ao);
                ldsm_x4(alo[mi], uAlo + ao);
            }
#pragma unroll
            for (int op = 0; op < 4; ++op) {
                uint32_t bo = (uint32_t)((warp_n * 64 + op * 16) * ROWB + ks * 32) + b_lo;
                uint32_t bh[4], bl[4];
                ldsm_x4(bh, uBhi + bo);
                ldsm_x4(bl, uBlo + bo);
#pragma unroll
                for (int hh = 0; hh < 2; ++hh) {
                    int ni = op * 2 + hh;
#pragma unroll
                    for (int mi = 0; mi < 2; ++mi) {
                        float* a = acc[mi][ni];
                        mma16816(a, ahi[mi][0], ahi[mi][1], ahi[mi][2], ahi[mi][3],
                                 bh[2 * hh], bh[2 * hh + 1]);
                        mma16816(a, ahi[mi][0], ahi[mi][1], ahi[mi][2], ahi[mi][3],
                                 bl[2 * hh], bl[2 * hh + 1]);
                        mma16816(a, alo[mi][0], alo[mi][1], alo[mi][2], alo[mi][3],
                                 bh[2 * hh], bh[2 * hh + 1]);
                    }
                }
            }
        }
        __syncthreads();
    }

    // ---- epilogue: feats hi/lo bf16 stores + inline a_self/a_neigh ----
    const int hh = (bn >> 6) + warp_n;   // this warp's head
    float ps0[2] = {0.f, 0.f}, ps1[2] = {0.f, 0.f};
    float pn0[2] = {0.f, 0.f}, pn1[2] = {0.f, 0.f};
#pragma unroll
    for (int mi = 0; mi < 2; ++mi) {
        int row = bm + warp_m * 32 + mi * 16 + lr;
#pragma unroll
        for (int ni = 0; ni < 8; ++ni) {
            int col = bn + warp_n * 64 + ni * 8 + lc * 2;
            float v0 = acc[mi][ni][0], v1 = acc[mi][ni][1];
            float v2 = acc[mi][ni][2], v3 = acc[mi][ni][3];
            __nv_bfloat16 h0 = __float2bfloat16(v0), h1 = __float2bfloat16(v1);
            __nv_bfloat16 h2 = __float2bfloat16(v2), h3 = __float2bfloat16(v3);
            *(__nv_bfloat162*)(g_fhi + (size_t)row * 512 + col) =
                __nv_bfloat162(h0, h1);
            *(__nv_bfloat162*)(g_fhi + (size_t)(row + 8) * 512 + col) =
                __nv_bfloat162(h2, h3);
            *(__nv_bfloat162*)(g_flo + (size_t)row * 512 + col) = __nv_bfloat162(
                __float2bfloat16(v0 - __bfloat162float(h0)),
                __float2bfloat16(v1 - __bfloat162float(h1)));
            *(__nv_bfloat162*)(g_flo + (size_t)(row + 8) * 512 + col) = __nv_bfloat162(
                __float2bfloat16(v2 - __bfloat162float(h2)),
                __float2bfloat16(v3 - __bfloat162float(h3)));
            float s0 = s_self[col], s1 = s_self[col + 1];
            float q0 = s_neigh[col], q1 = s_neigh[col + 1];
            ps0[mi] += v0 * s0 + v1 * s1;
            ps1[mi] += v2 * s0 + v3 * s1;
            pn0[mi] += v0 * q0 + v1 * q1;
            pn1[mi] += v2 * q0 + v3 * q1;
        }
    }
#pragma unroll
    for (int mi = 0; mi < 2; ++mi) {
        float a0 = ps0[mi], a1 = ps1[mi], c0 = pn0[mi], c1 = pn1[mi];
        a0 += __shfl_xor_sync(0xffffffffu, a0, 1); a0 += __shfl_xor_sync(0xffffffffu, a0, 2);
        a1 += __shfl_xor_sync(0xffffffffu, a1, 1); a1 += __shfl_xor_sync(0xffffffffu, a1, 2);
        c0 += __shfl_xor_sync(0xffffffffu, c0, 1); c0 += __shfl_xor_sync(0xffffffffu, c0, 2);
        c1 += __shfl_xor_sync(0xffffffffu, c1, 1); c1 += __shfl_xor_sync(0xffffffffu, c1, 2);
        if (lc == 0) {
            int row = bm + warp_m * 32 + mi * 16 + lr;
            g_asn[hh * 32768 + row] = a0;
            g_asn[hh * 32768 + row + 8] = a1;
            g_asn[262144 + hh * 32768 + row] = c0;
            g_asn[262144 + hh * 32768 + row + 8] = c1;
        }
    }
}

// ---------------------------------------------------------------------------
// K3: fused attention. mma aggregation with ldmatrix.x4 fragment loads.
// ---------------------------------------------------------------------------
#define AT_SFHI 0          // 32768: feats hi [256][64] bf16, XOR-swizzled
#define AT_SFLO 32768      // 32768: feats lo
#define AT_SWHI 65536      // 8448: attn hi [16][264] bf16 (528B rows)
#define AT_SWLO 73984      // 8448: attn lo
#define AT_SSEL 82432      // 64
#define AT_SRED 82496      // 512
#define AT_SINV 83008      // 64
#define AT_SIZE 83072

__global__ __launch_bounds__(256, 2) void attn_kernel(
    const float* __restrict__ Aadj, const float* __restrict__ biases,
    float* __restrict__ out, float* __restrict__ view) {
    extern __shared__ char smc[];
    const uint32_t sbase = smem_u32(smc);
    float* ssel = (float*)(smc + AT_SSEL);
    float* sred = (float*)(smc + AT_SRED);
    float* sinv = (float*)(smc + AT_SINV);

    const int b = blockIdx.y;
    const int i0 = blockIdx.x * 16;
    const int t = threadIdx.x;
    const int lane = t & 31, warp = t >> 5;
    const int gid = lane >> 2, tig = lane & 3;

    unsigned amask = 0u;
#pragma unroll
    for (int i = 0; i < 16; ++i)
        amask |= (Aadj[((size_t)b * 256 + i0 + i) * 256 + t] > 0.5f) ? (1u << i) : 0u;

    float vacc[16];
#pragma unroll
    for (int i = 0; i < 16; ++i) vacc[i] = 0.f;

    // per-lane ldmatrix offsets
    const uint32_t aw_lo = (uint32_t)((lane & 15) * 528 + ((lane >> 4) << 4));

    for (int h = 0; h < 8; ++h) {
        // --- feats hi/lo -> swizzled smem ([j][64] bf16, 128B rows) ---
#pragma unroll
        for (int i = 0; i < 8; ++i) {
            int q = t + 256 * i;           // 0..2047
            int j = q >> 3, c = q & 7;
            uint32_t so = j * 128 + ((c ^ (j & 7)) * 16);
            size_t g = (size_t)(b * 256 + j) * 512 + h * 64 + c * 8;
            *(uint4*)(smc + AT_SFHI + so) = *(const uint4*)(g_fhi + g);
            *(uint4*)(smc + AT_SFLO + so) = *(const uint4*)(g_flo + g);
        }
        if (t < 16) ssel[t] = g_asn[h * 32768 + b * 256 + i0 + t];
        float an = g_asn[262144 + h * 32768 + b * 256 + t];
        __syncthreads();

        // --- logits + exp (thread t = column j=t, 16 rows) ---
        float w[16];
#pragma unroll
        for (int i = 0; i < 16; ++i) {
            float z = ssel[i] + an;
            z = (z > 0.f) ? z : 0.2f * z;
            w[i] = ((amask >> i) & 1u) ? __expf(z) : 0.f;
        }
#pragma unroll
        for (int i = 0; i < 16; ++i) {
            float v = w[i];
#pragma unroll
            for (int o = 16; o > 0; o >>= 1) v += __shfl_xor_sync(0xffffffffu, v, o);
            if (lane == 0) sred[i * 8 + warp] = v;
        }
        __syncthreads();
        if (t < 16) {
            float s = 0.f;
#pragma unroll
            for (int g = 0; g < 8; ++g) s += sred[t * 8 + g];
            sinv[t] = 1.f / s;
        }
        __syncthreads();
#pragma unroll
        for (int i = 0; i < 16; ++i) {
            float a = w[i] * sinv[i];
            vacc[i] += 0.125f * a;
            __nv_bfloat16 ah = __float2bfloat16(a);
            *(__nv_bfloat16*)(smc + AT_SWHI + i * 528 + t * 2) = ah;
            *(__nv_bfloat16*)(smc + AT_SWLO + i * 528 + t * 2) =
                __float2bfloat16(a - __bfloat162float(ah));
        }
        __syncthreads();

        // --- node = attn @ feats via mma: warp owns n-tile of 8, full K=256 ---
        float acc[4] = {0.f, 0.f, 0.f, 0.f};
#pragma unroll
        for (int ks = 0; ks < 16; ++ks) {
            const int k0 = ks * 16;
            uint32_t ah[4], al[4];
            uint32_t ao = aw_lo + (uint32_t)(k0 * 2);
            ldsm_x4(ah, sbase + AT_SWHI + ao);
            ldsm_x4(al, sbase + AT_SWLO + ao);
            int r = k0 + (lane & 15);
            uint32_t bb = (uint32_t)((lane < 16 ? AT_SFHI : AT_SFLO) +
                                     r * 128 + ((warp ^ (r & 7)) << 4));
            uint32_t bf[4];
            ldsm_x4_t(bf, sbase + bb);
            mma16816(acc, ah[0], ah[1], ah[2], ah[3], bf[0], bf[1]);
            mma16816(acc, ah[0], ah[1], ah[2], ah[3], bf[2], bf[3]);
            mma16816(acc, al[0], al[1], al[2], al[3], bf[0], bf[1]);
        }
        // --- epilogue: bias + relu + direct store ---
        {
            int col = h * 64 + warp * 8 + tig * 2;
            float b0 = biases[col], b1 = biases[col + 1];
            float* o0 = out + (size_t)(b * 256 + i0 + gid) * 512 + col;
            *(float2*)o0 = make_float2(fmaxf(acc[0] + b0, 0.f), fmaxf(acc[1] + b1, 0.f));
            float* o1 = o0 + 8 * 512;
            *(float2*)o1 = make_float2(fmaxf(acc[2] + b0, 0.f), fmaxf(acc[3] + b1, 0.f));
        }
        __syncthreads();
    }

    // --- view store ---
#pragma unroll
    for (int i = 0; i < 16; ++i)
        view[((size_t)b * 256 + i0 + i) * 256 + t] = vacc[i];

    // --- 2x2 max pool + s[b] partial ---
    float part = 0.f;
    float rs = g_rowsum[t >> 1];
#pragma unroll
    for (int pi = 0; pi < 8; ++pi) {
        float rm = fmaxf(vacc[2 * pi], vacc[2 * pi + 1]);
        rm = fmaxf(rm, __shfl_xor_sync(0xffffffffu, rm, 1));
        if (!(t & 1)) part += rm * rs;
    }
#pragma unroll
    for (int o = 16; o > 0; o >>= 1) part += __shfl_xor_sync(0xffffffffu, part, o);
    if (lane == 0) atomicAdd(&g_s[b], part);
}

// ---------------------------------------------------------------------------
// K4: dense4 = (view + I < sigmoid(s[b])) ? 1 : 0
// ---------------------------------------------------------------------------
__global__ void binarize_kernel(float* __restrict__ view) {
    size_t idx = (size_t)blockIdx.x * 256 + threadIdx.x;
    int b = (int)(idx >> 16);
    int ij = (int)(idx & 65535);
    int i = ij >> 8, j = ij & 255;
    float th = 1.f / (1.f + expf(-g_s[b]));
    float v = view[idx] + ((i == j) ? 1.f : 0.f);
    view[idx] = (v < th) ? 1.f : 0.f;
}

// ---------------------------------------------------------------------------
extern "C" void kernel_launch(void* const* d_in, const int* in_sizes, int n_in,
                              void* d_out, int out_size) {
    const float* X          = (const float*)d_in[0];
    const float* Aadj       = (const float*)d_in[1];
    const float* kernels    = (const float*)d_in[2];
    const float* biases     = (const float*)d_in[3];
    const float* attn_self  = (const float*)d_in[4];
    const float* attn_neigh = (const float*)d_in[5];
    const float* alpha      = (const float*)d_in[6];
    float* out  = (float*)d_out;            // [128,256,512]
    float* view = out + 16777216;           // dense4 region [128,256,256]

    cudaFuncSetAttribute(attn_kernel, cudaFuncAttributeMaxDynamicSharedMemorySize, AT_SIZE);

    convx_kernel<<<65536, 256>>>(X);
    prep_kernel<<<1024, 256>>>(kernels, alpha);
    mma_gemm_kernel<<<dim3(4, 256), 256>>>(attn_self, attn_neigh);
    attn_kernel<<<dim3(16, 128), 256, AT_SIZE>>>(Aadj, biases, out, view);
    binarize_kernel<<<32768, 256>>>(view);
}

// round 12
// speedup vs baseline: 2.7839x; 1.2737x over previous
#include <cuda_runtime.h>
#include <cuda_bf16.h>
#include <cstdint>

// ---------------------------------------------------------------------------
// GraphAttention: B=128, N=256, F=512, H=8, F_=64
// Output d_out: concat( output [128,256,512], dense4 [128,256,256] ) f32
// ---------------------------------------------------------------------------

__device__ float g_asn[524288];                // a_self [8][32768], a_neigh [8][32768]
__device__ float g_rowsum[128];
__device__ float g_s[128];
__device__ __nv_bfloat16 g_Whi[262144];        // W^T hi: [n=512][f=512]
__device__ __nv_bfloat16 g_Wlo[262144];        // W^T lo
__device__ __nv_bfloat16 g_fhi[16777216];      // feats hi [32768][512]
__device__ __nv_bfloat16 g_flo[16777216];      // feats lo

__device__ __forceinline__ uint32_t smem_u32(const void* p) {
    uint32_t a;
    asm("{ .reg .u64 t; cvta.to.shared.u64 t, %1; cvt.u32.u64 %0, t; }" : "=r"(a) : "l"(p));
    return a;
}
__device__ __forceinline__ void mma16816(float* c, uint32_t a0, uint32_t a1,
                                         uint32_t a2, uint32_t a3,
                                         uint32_t b0, uint32_t b1) {
    asm volatile(
        "mma.sync.aligned.m16n8k16.row.col.f32.bf16.bf16.f32 "
        "{%0,%1,%2,%3}, {%4,%5,%6,%7}, {%8,%9}, {%0,%1,%2,%3};"
        : "+f"(c[0]), "+f"(c[1]), "+f"(c[2]), "+f"(c[3])
        : "r"(a0), "r"(a1), "r"(a2), "r"(a3), "r"(b0), "r"(b1));
}
__device__ __forceinline__ void ldsm_x4(uint32_t* r, uint32_t addr) {
    asm volatile("ldmatrix.sync.aligned.m8n8.x4.shared.b16 {%0,%1,%2,%3}, [%4];"
                 : "=r"(r[0]), "=r"(r[1]), "=r"(r[2]), "=r"(r[3]) : "r"(addr));
}
__device__ __forceinline__ void ldsm_x4_t(uint32_t* r, uint32_t addr) {
    asm volatile("ldmatrix.sync.aligned.m8n8.x4.trans.shared.b16 {%0,%1,%2,%3}, [%4];"
                 : "=r"(r[0]), "=r"(r[1]), "=r"(r[2]), "=r"(r[3]) : "r"(addr));
}
__device__ __forceinline__ void cp16(uint32_t dst, const void* src) {
    asm volatile("cp.async.cg.shared.global [%0], [%1], 16;" :: "r"(dst), "l"(src));
}
#define CP_COMMIT() asm volatile("cp.async.commit_group;" ::: "memory")
#define CP_WAIT0()  asm volatile("cp.async.wait_group 0;" ::: "memory")

// split 8 fp32 -> 8 bf16 hi + 8 bf16 lo (packed uint4 each)
__device__ __forceinline__ void split8(const float* xp, uint4* hi, uint4* lo) {
    float4 x0 = *(const float4*)xp;
    float4 x1 = *(const float4*)(xp + 4);
    float xs[8] = {x0.x, x0.y, x0.z, x0.w, x1.x, x1.y, x1.z, x1.w};
    __nv_bfloat16 hb[8], lb[8];
#pragma unroll
    for (int i = 0; i < 8; ++i) {
        hb[i] = __float2bfloat16(xs[i]);
        lb[i] = __float2bfloat16(xs[i] - __bfloat162float(hb[i]));
    }
    *hi = *(uint4*)hb;
    *lo = *(uint4*)lb;
}

// ---------------------------------------------------------------------------
// K0: W^T split to bf16 hi/lo, alpha row sums, zero g_s
// ---------------------------------------------------------------------------
__global__ void prep_kernel(const float* __restrict__ kernels,
                            const float* __restrict__ alpha) {
    int idx = blockIdx.x * 256 + threadIdx.x;
    if (idx < 262144) {
        int n = idx >> 9, f = idx & 511;
        int h = n >> 6, kk = n & 63;
        float v = kernels[(h * 512 + f) * 64 + kk];
        __nv_bfloat16 hi = __float2bfloat16(v);
        g_Whi[idx] = hi;
        g_Wlo[idx] = __float2bfloat16(v - __bfloat162float(hi));
    }
    if (idx < 128) {
        float s = 0.f;
        const float* ar = alpha + idx * 128;
#pragma unroll 4
        for (int k = 0; k < 128; ++k) s += ar[k];
        g_rowsum[idx] = s;
        g_s[idx] = 0.f;
    }
}

// ---------------------------------------------------------------------------
// K1: feats = X @ W via mma.sync bf16 split. X loaded fp32 + split in-kernel
// (convx folded in); W tiles via cp.async. Epilogue: feats hi/lo + asn inline.
// ---------------------------------------------------------------------------
#define ROWB 80  // bytes per smem row (32 bf16 data + 8 pad)

__global__ __launch_bounds__(256, 2) void mma_gemm_kernel(
    const float* __restrict__ X,
    const float* __restrict__ attn_self, const float* __restrict__ attn_neigh) {
    __shared__ __align__(16) char sAhi[128 * ROWB];
    __shared__ __align__(16) char sAlo[128 * ROWB];
    __shared__ __align__(16) char sBhi[128 * ROWB];
    __shared__ __align__(16) char sBlo[128 * ROWB];
    __shared__ float s_self[512], s_neigh[512];

    const int t = threadIdx.x;
    const int lane = t & 31, warp = t >> 5;
    const int warp_m = warp & 3;
    const int warp_n = warp >> 2;
    const int lr = lane >> 2, lc = lane & 3;
    const int bm = blockIdx.y * 128;
    const int bn = blockIdx.x * 128;
    const uint32_t uAhi = smem_u32(sAhi), uAlo = smem_u32(sAlo);
    const uint32_t uBhi = smem_u32(sBhi), uBlo = smem_u32(sBlo);

    for (int u = t; u < 512; u += 256) { s_self[u] = attn_self[u]; s_neigh[u] = attn_neigh[u]; }

    float acc[2][8][4];
#pragma unroll
    for (int mi = 0; mi < 2; ++mi)
#pragma unroll
        for (int ni = 0; ni < 8; ++ni)
#pragma unroll
            for (int r = 0; r < 4; ++r) acc[mi][ni][r] = 0.f;

    const uint32_t a_lo = (uint32_t)((lane & 15) * ROWB + ((lane >> 4) << 4));
    const uint32_t b_lo = (uint32_t)((((lane >> 4) << 3) + (lane & 7)) * ROWB +
                                     (((lane >> 3) & 1) << 4));

    for (int c = 0; c < 16; ++c) {
        const int k0 = c * 32;
        // ---- B (W hi/lo) via cp.async ----
#pragma unroll
        for (int i = 0; i < 2; ++i) {
            int qq = t + 256 * i;          // 0..511
            int row = qq >> 2, c8 = qq & 3;
            uint32_t soff = row * ROWB + c8 * 16;
            size_t gb = (size_t)(bn + row) * 512 + k0 + c8 * 8;
            cp16(uBhi + soff, g_Whi + gb);
            cp16(uBlo + soff, g_Wlo + gb);
        }
        CP_COMMIT();
        // ---- A: X fp32 load + split -> smem ----
#pragma unroll
        for (int i = 0; i < 2; ++i) {
            int qq = t + 256 * i;
            int row = qq >> 2, c8 = qq & 3;
            uint32_t soff = row * ROWB + c8 * 16;
            uint4 hi, lo;
            split8(X + (size_t)(bm + row) * 512 + k0 + c8 * 8, &hi, &lo);
            *(uint4*)(sAhi + soff) = hi;
            *(uint4*)(sAlo + soff) = lo;
        }
        CP_WAIT0();
        __syncthreads();

#pragma unroll
        for (int ks = 0; ks < 2; ++ks) {
            uint32_t ahi[2][4], alo[2][4];
#pragma unroll
            for (int mi = 0; mi < 2; ++mi) {
                uint32_t ao = (uint32_t)((warp_m * 32 + mi * 16) * ROWB + ks * 32) + a_lo;
                ldsm_x4(ahi[mi], uAhi + ao);
                ldsm_x4(alo[mi], uAlo + ao);
            }
#pragma unroll
            for (int op = 0; op < 4; ++op) {
                uint32_t bo = (uint32_t)((warp_n * 64 + op * 16) * ROWB + ks * 32) + b_lo;
                uint32_t bh[4], bl[4];
                ldsm_x4(bh, uBhi + bo);
                ldsm_x4(bl, uBlo + bo);
#pragma unroll
                for (int hh = 0; hh < 2; ++hh) {
                    int ni = op * 2 + hh;
#pragma unroll
                    for (int mi = 0; mi < 2; ++mi) {
                        float* a = acc[mi][ni];
                        mma16816(a, ahi[mi][0], ahi[mi][1], ahi[mi][2], ahi[mi][3],
                                 bh[2 * hh], bh[2 * hh + 1]);
                        mma16816(a, ahi[mi][0], ahi[mi][1], ahi[mi][2], ahi[mi][3],
                                 bl[2 * hh], bl[2 * hh + 1]);
                        mma16816(a, alo[mi][0], alo[mi][1], alo[mi][2], alo[mi][3],
                                 bh[2 * hh], bh[2 * hh + 1]);
                    }
                }
            }
        }
        __syncthreads();
    }

    // ---- epilogue: feats hi/lo bf16 stores + inline a_self/a_neigh ----
    const int hh = (bn >> 6) + warp_n;
    float ps0[2] = {0.f, 0.f}, ps1[2] = {0.f, 0.f};
    float pn0[2] = {0.f, 0.f}, pn1[2] = {0.f, 0.f};
#pragma unroll
    for (int mi = 0; mi < 2; ++mi) {
        int row = bm + warp_m * 32 + mi * 16 + lr;
#pragma unroll
        for (int ni = 0; ni < 8; ++ni) {
            int col = bn + warp_n * 64 + ni * 8 + lc * 2;
            float v0 = acc[mi][ni][0], v1 = acc[mi][ni][1];
            float v2 = acc[mi][ni][2], v3 = acc[mi][ni][3];
            __nv_bfloat16 h0 = __float2bfloat16(v0), h1 = __float2bfloat16(v1);
            __nv_bfloat16 h2 = __float2bfloat16(v2), h3 = __float2bfloat16(v3);
            *(__nv_bfloat162*)(g_fhi + (size_t)row * 512 + col) = __nv_bfloat162(h0, h1);
            *(__nv_bfloat162*)(g_fhi + (size_t)(row + 8) * 512 + col) = __nv_bfloat162(h2, h3);
            *(__nv_bfloat162*)(g_flo + (size_t)row * 512 + col) = __nv_bfloat162(
                __float2bfloat16(v0 - __bfloat162float(h0)),
                __float2bfloat16(v1 - __bfloat162float(h1)));
            *(__nv_bfloat162*)(g_flo + (size_t)(row + 8) * 512 + col) = __nv_bfloat162(
                __float2bfloat16(v2 - __bfloat162float(h2)),
                __float2bfloat16(v3 - __bfloat162float(h3)));
            float s0 = s_self[col], s1 = s_self[col + 1];
            float q0 = s_neigh[col], q1 = s_neigh[col + 1];
            ps0[mi] += v0 * s0 + v1 * s1;
            ps1[mi] += v2 * s0 + v3 * s1;
            pn0[mi] += v0 * q0 + v1 * q1;
            pn1[mi] += v2 * q0 + v3 * q1;
        }
    }
#pragma unroll
    for (int mi = 0; mi < 2; ++mi) {
        float a0 = ps0[mi], a1 = ps1[mi], c0 = pn0[mi], c1 = pn1[mi];
        a0 += __shfl_xor_sync(0xffffffffu, a0, 1); a0 += __shfl_xor_sync(0xffffffffu, a0, 2);
        a1 += __shfl_xor_sync(0xffffffffu, a1, 1); a1 += __shfl_xor_sync(0xffffffffu, a1, 2);
        c0 += __shfl_xor_sync(0xffffffffu, c0, 1); c0 += __shfl_xor_sync(0xffffffffu, c0, 2);
        c1 += __shfl_xor_sync(0xffffffffu, c1, 1); c1 += __shfl_xor_sync(0xffffffffu, c1, 2);
        if (lc == 0) {
            int row = bm + warp_m * 32 + mi * 16 + lr;
            g_asn[hh * 32768 + row] = a0;
            g_asn[hh * 32768 + row + 8] = a1;
            g_asn[262144 + hh * 32768 + row] = c0;
            g_asn[262144 + hh * 32768 + row + 8] = c1;
        }
    }
}

// ---------------------------------------------------------------------------
// K3: fused attention v4: unnormalized-w mma + ones-mma rowsums (no shuffle
// softmax reduction), cp.async fills, 3 barriers/head.
// ---------------------------------------------------------------------------
#define AT_SFHI 0          // 32768: feats hi [256][64] bf16, XOR-swizzled
#define AT_SFLO 32768      // 32768: feats lo
#define AT_SWHI 65536      // 8448: w hi [16][264] bf16 (528B rows), unnormalized
#define AT_SWLO 73984      // 8448: w lo
#define AT_SSEL 82432      // 64
#define AT_SINV 82496      // 64
#define AT_SIZE 82560

__global__ __launch_bounds__(256, 2) void attn_kernel(
    const float* __restrict__ Aadj, const float* __restrict__ biases,
    float* __restrict__ out, float* __restrict__ view) {
    extern __shared__ char smc[];
    const uint32_t sbase = smem_u32(smc);
    float* ssel = (float*)(smc + AT_SSEL);
    float* sinv = (float*)(smc + AT_SINV);

    const int b = blockIdx.y;
    const int i0 = blockIdx.x * 16;
    const int t = threadIdx.x;
    const int lane = t & 31, warp = t >> 5;
    const int gid = lane >> 2, tig = lane & 3;
    const uint32_t ONES = 0x3F803F80u;  // bf16 (1.0, 1.0)

    unsigned amask = 0u;
#pragma unroll
    for (int i = 0; i < 16; ++i)
        amask |= (Aadj[((size_t)b * 256 + i0 + i) * 256 + t] > 0.5f) ? (1u << i) : 0u;

    float vacc[16];
#pragma unroll
    for (int i = 0; i < 16; ++i) vacc[i] = 0.f;

    const uint32_t aw_lo = (uint32_t)((lane & 15) * 528 + ((lane >> 4) << 4));

    for (int h = 0; h < 8; ++h) {
        // --- feats hi/lo -> swizzled smem via cp.async ---
#pragma unroll
        for (int i = 0; i < 8; ++i) {
            int q = t + 256 * i;           // 0..2047
            int j = q >> 3, c = q & 7;
            uint32_t so = (uint32_t)(j * 128 + ((c ^ (j & 7)) * 16));
            size_t g = (size_t)(b * 256 + j) * 512 + h * 64 + c * 8;
            cp16(sbase + AT_SFHI + so, g_fhi + g);
            cp16(sbase + AT_SFLO + so, g_flo + g);
        }
        CP_COMMIT();
        if (t < 16) ssel[t] = g_asn[h * 32768 + b * 256 + i0 + t];
        float an = g_asn[262144 + h * 32768 + b * 256 + t];
        CP_WAIT0();
        __syncthreads();                                   // B1

        // --- logits + exp; store UNNORMALIZED w hi/lo ---
        float w[16];
#pragma unroll
        for (int i = 0; i < 16; ++i) {
            float z = ssel[i] + an;
            z = (z > 0.f) ? z : 0.2f * z;
            w[i] = ((amask >> i) & 1u) ? __expf(z) : 0.f;
            __nv_bfloat16 wh = __float2bfloat16(w[i]);
            *(__nv_bfloat16*)(smc + AT_SWHI + i * 528 + t * 2) = wh;
            *(__nv_bfloat16*)(smc + AT_SWLO + i * 528 + t * 2) =
                __float2bfloat16(w[i] - __bfloat162float(wh));
        }
        __syncthreads();                                   // B2

        // --- mma: data (3) + ones rowsum (2) per kstep ---
        float acc[4] = {0.f, 0.f, 0.f, 0.f};
        float accR[4] = {0.f, 0.f, 0.f, 0.f};
#pragma unroll
        for (int ks = 0; ks < 16; ++ks) {
            const int k0 = ks * 16;
            uint32_t ah[4], al[4];
            uint32_t ao = aw_lo + (uint32_t)(k0 * 2);
            ldsm_x4(ah, sbase + AT_SWHI + ao);
            ldsm_x4(al, sbase + AT_SWLO + ao);
            int r = k0 + (lane & 15);
            uint32_t bb = (uint32_t)((lane < 16 ? AT_SFHI : AT_SFLO) +
                                     r * 128 + ((warp ^ (r & 7)) << 4));
            uint32_t bf[4];
            ldsm_x4_t(bf, sbase + bb);
            mma16816(acc, ah[0], ah[1], ah[2], ah[3], bf[0], bf[1]);
            mma16816(acc, ah[0], ah[1], ah[2], ah[3], bf[2], bf[3]);
            mma16816(acc, al[0], al[1], al[2], al[3], bf[0], bf[1]);
            mma16816(accR, ah[0], ah[1], ah[2], ah[3], ONES, ONES);
            mma16816(accR, al[0], al[1], al[2], al[3], ONES, ONES);
        }
        // --- normalize + bias + relu + store; broadcast inv ---
        float inv0 = 1.f / accR[0];
        float inv1 = 1.f / accR[2];
        if (warp == 0 && tig == 0) { sinv[gid] = inv0; sinv[gid + 8] = inv1; }
        {
            int col = h * 64 + warp * 8 + tig * 2;
            float b0 = biases[col], b1 = biases[col + 1];
            float* o0 = out + (size_t)(b * 256 + i0 + gid) * 512 + col;
            *(float2*)o0 = make_float2(fmaxf(acc[0] * inv0 + b0, 0.f),
                                       fmaxf(acc[1] * inv0 + b1, 0.f));
            float* o1 = o0 + 8 * 512;
            *(float2*)o1 = make_float2(fmaxf(acc[2] * inv1 + b0, 0.f),
                                       fmaxf(acc[3] * inv1 + b1, 0.f));
        }
        __syncthreads();                                   // B3
        // --- view accumulation with full-precision register w ---
#pragma unroll
        for (int i = 0; i < 16; ++i)
            vacc[i] += 0.125f * w[i] * sinv[i];
    }

    // --- view store ---
#pragma unroll
    for (int i = 0; i < 16; ++i)
        view[((size_t)b * 256 + i0 + i) * 256 + t] = vacc[i];

    // --- 2x2 max pool + s[b] partial ---
    float part = 0.f;
    float rs = g_rowsum[t >> 1];
#pragma unroll
    for (int pi = 0; pi < 8; ++pi) {
        float rm = fmaxf(vacc[2 * pi], vacc[2 * pi + 1]);
        rm = fmaxf(rm, __shfl_xor_sync(0xffffffffu, rm, 1));
        if (!(t & 1)) part += rm * rs;
    }
#pragma unroll
    for (int o = 16; o > 0; o >>= 1) part += __shfl_xor_sync(0xffffffffu, part, o);
    if (lane == 0) atomicAdd(&g_s[b], part);
}

// ---------------------------------------------------------------------------
// K4: dense4 = (view + I < sigmoid(s[b])) ? 1 : 0
// ---------------------------------------------------------------------------
__global__ void binarize_kernel(float* __restrict__ view) {
    size_t idx = (size_t)blockIdx.x * 256 + threadIdx.x;
    int b = (int)(idx >> 16);
    int ij = (int)(idx & 65535);
    int i = ij >> 8, j = ij & 255;
    float th = 1.f / (1.f + expf(-g_s[b]));
    float v = view[idx] + ((i == j) ? 1.f : 0.f);
    view[idx] = (v < th) ? 1.f : 0.f;
}

// ---------------------------------------------------------------------------
extern "C" void kernel_launch(void* const* d_in, const int* in_sizes, int n_in,
                              void* d_out, int out_size) {
    const float* X          = (const float*)d_in[0];
    const float* Aadj       = (const float*)d_in[1];
    const float* kernels    = (const float*)d_in[2];
    const float* biases     = (const float*)d_in[3];
    const float* attn_self  = (const float*)d_in[4];
    const float* attn_neigh = (const float*)d_in[5];
    const float* alpha      = (const float*)d_in[6];
    float* out  = (float*)d_out;            // [128,256,512]
    float* view = out + 16777216;           // dense4 region [128,256,256]

    cudaFuncSetAttribute(attn_kernel, cudaFuncAttributeMaxDynamicSharedMemorySize, AT_SIZE);

    prep_kernel<<<1024, 256>>>(kernels, alpha);
    mma_gemm_kernel<<<dim3(4, 256), 256>>>(X, attn_self, attn_neigh);
    attn_kernel<<<dim3(16, 128), 256, AT_SIZE>>>(Aadj, biases, out, view);
    binarize_kernel<<<32768, 256>>>(view);
}